// round 12
// baseline (speedup 1.0000x reference)
#include <cuda_runtime.h>
#include <cuda_bf16.h>
#include <math.h>
#include <stdint.h>

#define S_LEN 2048
#define DM    1024
#define NH    16
#define HD    64
#define BATCH 2
#define BHN   (BATCH * NH)        // 32
#define MROWS (BATCH * S_LEN)     // 4096
#define KC2   2048                // [hi|lo] interleaved per 32-k chunk
#define NCH2  32                  // 32 chunks of 32 k-elems
#define QK2   128                 // Q/K row: [hi 64 | lo 64]

// ---------------- scratch (__device__ globals) ------------------------------
__device__ __nv_bfloat16 g_Xcat[(size_t)MROWS * KC2];
__device__ __nv_bfloat16 g_Acat[(size_t)MROWS * KC2];
__device__ __nv_bfloat16 g_Wqc[(size_t)DM * KC2];
__device__ __nv_bfloat16 g_Wkc[(size_t)DM * KC2];
__device__ __nv_bfloat16 g_Wvc[(size_t)DM * KC2];
__device__ __nv_bfloat16 g_Woc[(size_t)DM * KC2];
__device__ __nv_bfloat16 g_Qc[(size_t)BHN * S_LEN * QK2];   // [hi|lo]
__device__ __nv_bfloat16 g_Kc[(size_t)BHN * S_LEN * QK2];   // [hi|lo]
__device__ __nv_bfloat16 g_Vth[(size_t)BHN * HD * S_LEN];   // V^T hi
__device__ __nv_bfloat16 g_Vtl[(size_t)BHN * HD * S_LEN];   // V^T lo

// ---------------- helpers ---------------------------------------------------
__device__ __forceinline__ uint32_t smem_u32(const void* p) {
    uint32_t a;
    asm("{ .reg .u64 t; cvta.to.shared.u64 t, %1; cvt.u32.u64 %0, t; }"
        : "=r"(a) : "l"(p));
    return a;
}
#define SW128(o) ((o) ^ (((o) >> 3) & 0x70))

__device__ __forceinline__ void ldm_x4(uint32_t* r, uint32_t addr) {
    asm volatile("ldmatrix.sync.aligned.m8n8.x4.shared.b16 {%0,%1,%2,%3}, [%4];"
                 : "=r"(r[0]), "=r"(r[1]), "=r"(r[2]), "=r"(r[3]) : "r"(addr));
}
__device__ __forceinline__ void mma_bf16(float* c, const uint32_t* a,
                                         uint32_t b0, uint32_t b1) {
    asm volatile(
        "mma.sync.aligned.m16n8k16.row.col.f32.bf16.bf16.f32 "
        "{%0,%1,%2,%3}, {%4,%5,%6,%7}, {%8,%9}, {%0,%1,%2,%3};"
        : "+f"(c[0]), "+f"(c[1]), "+f"(c[2]), "+f"(c[3])
        : "r"(a[0]), "r"(a[1]), "r"(a[2]), "r"(a[3]), "r"(b0), "r"(b1));
}
#define CP16(dst, src) \
    asm volatile("cp.async.cg.shared.global [%0], [%1], 16;" :: "r"(dst), "l"(src))
#define CP_COMMIT() asm volatile("cp.async.commit_group;")

// ---------------------------------------------------------------------------
// fp32 [rows,1024] -> bf16 [rows,2048], per-32-chunk interleave [hi32|lo32].
// ---------------------------------------------------------------------------
__global__ __launch_bounds__(256) void convert_cat(
    const float* __restrict__ src, __nv_bfloat16* __restrict__ dst, int rows)
{
    int n = rows * (DM / 4);
    for (int i = blockIdx.x * blockDim.x + threadIdx.x; i < n;
         i += gridDim.x * blockDim.x) {
        int r = i / (DM / 4), cq = i - r * (DM / 4);
        float4 v = *(const float4*)&src[(size_t)r * DM + cq * 4];
        float f[4] = {v.x, v.y, v.z, v.w};
        __nv_bfloat16 hi[4], lo[4];
#pragma unroll
        for (int j = 0; j < 4; j++) {
            hi[j] = __float2bfloat16(f[j]);
            lo[j] = __float2bfloat16(f[j] - __bfloat162float(hi[j]));
        }
        int c = cq >> 3;
        int p = (cq & 7) * 4;
        size_t base = (size_t)r * KC2 + c * 64 + p;
        *(__nv_bfloat162*)&dst[base]      = __halves2bfloat162(hi[0], hi[1]);
        *(__nv_bfloat162*)&dst[base + 2]  = __halves2bfloat162(hi[2], hi[3]);
        *(__nv_bfloat162*)&dst[base + 32] = __halves2bfloat162(lo[0], lo[1]);
        *(__nv_bfloat162*)&dst[base + 34] = __halves2bfloat162(lo[2], lo[3]);
    }
}

// ---------------------------------------------------------------------------
// mma.sync bf16 GEMM: C[r,c] = sum_k A[r,k]*B[c,k] + bias[c]
// Operands [rows, 2048] interleaved [hi|lo] per 32-chunk. Per chunk: 3 passes
// Ah*Bh + Ah*Bl + Al*Bh with fragment reuse. 3-stage cp.async, 2 CTAs/SM.
// omode 0: fp32 row-major.  1: Q/K split [hi|lo].  3: V^T hi/lo planes.
// ---------------------------------------------------------------------------
#define GEMM_SMEM 98304   // A: 3x16K at 0, B: 3x16K at 49152

__global__ void __launch_bounds__(256, 2) gemm_mma(
    const __nv_bfloat16* __restrict__ A, const __nv_bfloat16* __restrict__ B,
    const float* __restrict__ bias, float* __restrict__ outf,
    __nv_bfloat16* __restrict__ ob1, __nv_bfloat16* __restrict__ ob2, int omode)
{
    extern __shared__ __align__(1024) char smem[];
    const int tid = threadIdx.x;
    const int wid = tid >> 5, lane = tid & 31;
    const int warp_m = wid >> 2;
    const int warp_n = wid & 3;
    const uint32_t sb = smem_u32(smem);

    const int r0 = blockIdx.y * 128, c0 = blockIdx.x * 128;
    const int ls = tid & 7;
    const int lr = tid >> 3;

#define LOAD_STAGE(chunk, stage) do {                                          \
        uint32_t ab = sb + (stage) * 16384;                                    \
        uint32_t bb = sb + 49152 + (stage) * 16384;                            \
        size_t kb = (size_t)(chunk) * 64 + ls * 8;                             \
        _Pragma("unroll")                                                      \
        for (int i_ = 0; i_ < 4; i_++) {                                       \
            int r_ = lr + 32 * i_;                                             \
            uint32_t off = SW128(r_ * 128 + ls * 16);                          \
            CP16(ab + off, &A[(size_t)(r0 + r_) * KC2 + kb]);                  \
            CP16(bb + off, &B[(size_t)(c0 + r_) * KC2 + kb]);                  \
        }                                                                      \
        CP_COMMIT();                                                           \
    } while (0)

    float acc[4][4][4] = {};
    LOAD_STAGE(0, 0);
    LOAD_STAGE(1, 1);

    int st = 0, st2 = 2;
    for (int c = 0; c < NCH2; c++) {
        if (c + 2 < NCH2) LOAD_STAGE(c + 2, st2);
        else              CP_COMMIT();
        asm volatile("cp.async.wait_group 2;");
        __syncthreads();

        const uint32_t abase = sb + st * 16384;
        const uint32_t bbase = sb + 49152 + st * 16384;
#pragma unroll
        for (int ks = 0; ks < 2; ks++) {
            uint32_t af[4][4];
            uint32_t bh[2][4], bl[2][4];
#pragma unroll
            for (int mt = 0; mt < 4; mt++) {
                int row = warp_m * 64 + mt * 16 + (lane & 15);
                int seg = ks * 2 + (lane >> 4);
                ldm_x4(af[mt], abase + SW128(row * 128 + seg * 16));
            }
#pragma unroll
            for (int h = 0; h < 2; h++) {
                int row = warp_n * 32 + h * 16 + ((lane >> 4) & 1) * 8 + (lane & 7);
                int seg = ks * 2 + ((lane >> 3) & 1);
                uint32_t off = row * 128 + seg * 16;
                ldm_x4(bh[h], bbase + SW128(off));
                ldm_x4(bl[h], bbase + SW128(off + 64));
            }
#pragma unroll
            for (int mt = 0; mt < 4; mt++)
#pragma unroll
                for (int nt = 0; nt < 4; nt++)
                    mma_bf16(acc[mt][nt], af[mt],
                             bh[nt >> 1][(nt & 1) * 2], bh[nt >> 1][(nt & 1) * 2 + 1]);
#pragma unroll
            for (int mt = 0; mt < 4; mt++)
#pragma unroll
                for (int nt = 0; nt < 4; nt++)
                    mma_bf16(acc[mt][nt], af[mt],
                             bl[nt >> 1][(nt & 1) * 2], bl[nt >> 1][(nt & 1) * 2 + 1]);
#pragma unroll
            for (int mt = 0; mt < 4; mt++) {
                int row = warp_m * 64 + mt * 16 + (lane & 15);
                int seg = 4 + ks * 2 + (lane >> 4);
                ldm_x4(af[mt], abase + SW128(row * 128 + seg * 16));
            }
#pragma unroll
            for (int mt = 0; mt < 4; mt++)
#pragma unroll
                for (int nt = 0; nt < 4; nt++)
                    mma_bf16(acc[mt][nt], af[mt],
                             bh[nt >> 1][(nt & 1) * 2], bh[nt >> 1][(nt & 1) * 2 + 1]);
        }
        __syncthreads();
        st  = (st  == 2) ? 0 : st + 1;
        st2 = (st2 == 2) ? 0 : st2 + 1;
    }
#undef LOAD_STAGE

    const int mrow = lane >> 2;
    const int ncol = 2 * (lane & 3);
#pragma unroll
    for (int mt = 0; mt < 4; mt++) {
#pragma unroll
        for (int nt = 0; nt < 4; nt++) {
            int cg = c0 + warp_n * 32 + nt * 8 + ncol;
            float b0 = __ldg(&bias[cg]), b1 = __ldg(&bias[cg + 1]);
#pragma unroll
            for (int half = 0; half < 2; half++) {
                int r = r0 + warp_m * 64 + mt * 16 + mrow + half * 8;
                float v0 = acc[mt][nt][half * 2] + b0;
                float v1 = acc[mt][nt][half * 2 + 1] + b1;
                if (omode == 0) {
                    float2 v = {v0, v1};
                    *(float2*)&outf[(size_t)r * DM + cg] = v;
                } else {
                    int bb = r >> 11, s = r & (S_LEN - 1);
                    int h = cg >> 6, hd = cg & 63;
                    __nv_bfloat16 h0 = __float2bfloat16(v0);
                    __nv_bfloat16 h1 = __float2bfloat16(v1);
                    __nv_bfloat16 l0 = __float2bfloat16(v0 - __bfloat162float(h0));
                    __nv_bfloat16 l1 = __float2bfloat16(v1 - __bfloat162float(h1));
                    if (omode == 3) {
                        size_t pb = ((size_t)(bb * NH + h) * HD + hd) * S_LEN + s;
                        ob1[pb] = h0; ob1[pb + S_LEN] = h1;
                        ob2[pb] = l0; ob2[pb + S_LEN] = l1;
                    } else {
                        size_t base = ((size_t)(bb * NH + h) * S_LEN + s) * QK2 + hd;
                        *(__nv_bfloat162*)&ob1[base]      = __halves2bfloat162(h0, h1);
                        *(__nv_bfloat162*)&ob1[base + 64] = __halves2bfloat162(l0, l1);
                    }
                }
            }
        }
    }
}

// ---------------------------------------------------------------------------
// scores_mma: attn = 0.125 * (Qh*Kh + Qh*Kl + Ql*Kh).  Q/K rows [hi|lo] (128).
// Upper-triangle CTAs (kt > qt) zero-fill their attn tile instead of exiting.
// ---------------------------------------------------------------------------
#define SC_SMEM 65536

__global__ __launch_bounds__(256) void scores_mma(
    const __nv_bfloat16* __restrict__ Qc, const __nv_bfloat16* __restrict__ Kc,
    float* __restrict__ attn)
{
    const int kt = blockIdx.x, qt = blockIdx.y, bh = blockIdx.z;
    const int q0 = qt * 128, c0 = kt * 128;
    float* Arow = attn + (size_t)bh * S_LEN * S_LEN;

    if (kt > qt) {
        const float4 z = {0.f, 0.f, 0.f, 0.f};
        const int tid = threadIdx.x;
        for (int idx = tid; idx < 128 * 32; idx += 256) {
            int r = idx >> 5, c = (idx & 31) * 4;
            *(float4*)&Arow[(size_t)(q0 + r) * S_LEN + c0 + c] = z;
        }
        return;
    }

    extern __shared__ __align__(1024) char smem[];
    const int tid = threadIdx.x;
    const int wid = tid >> 5, lane = tid & 31;
    const int warp_m = wid >> 2;
    const int warp_n = wid & 3;
    const uint32_t sb = smem_u32(smem);

    const __nv_bfloat16* Qb = Qc + (size_t)bh * S_LEN * QK2;
    const __nv_bfloat16* Kb = Kc + (size_t)bh * S_LEN * QK2;
    const int ls = tid & 7;
    const int lr = tid >> 3;

#pragma unroll
    for (int i_ = 0; i_ < 4; i_++) {
        int r_ = lr + 32 * i_;
        uint32_t off = SW128(r_ * 128 + ls * 16);
        CP16(sb + off,         &Qb[(size_t)(q0 + r_) * QK2 + ls * 8]);
        CP16(sb + 16384 + off, &Qb[(size_t)(q0 + r_) * QK2 + 64 + ls * 8]);
        CP16(sb + 32768 + off, &Kb[(size_t)(c0 + r_) * QK2 + ls * 8]);
        CP16(sb + 49152 + off, &Kb[(size_t)(c0 + r_) * QK2 + 64 + ls * 8]);
    }
    CP_COMMIT();
    asm volatile("cp.async.wait_group 0;");
    __syncthreads();

    float acc[4][4][4] = {};
#pragma unroll
    for (int ks = 0; ks < 4; ks++) {
        uint32_t af[4][4], bh[2][4], bl[2][4];
#pragma unroll
        for (int mt = 0; mt < 4; mt++) {
            int row = warp_m * 64 + mt * 16 + (lane & 15);
            int seg = ks * 2 + (lane >> 4);
            ldm_x4(af[mt], sb + SW128(row * 128 + seg * 16));
        }
#pragma unroll
        for (int h = 0; h < 2; h++) {
            int row = warp_n * 32 + h * 16 + ((lane >> 4) & 1) * 8 + (lane & 7);
            int seg = ks * 2 + ((lane >> 3) & 1);
            uint32_t off = SW128(row * 128 + seg * 16);
            ldm_x4(bh[h], sb + 32768 + off);
            ldm_x4(bl[h], sb + 49152 + off);
        }
#pragma unroll
        for (int mt = 0; mt < 4; mt++)
#pragma unroll
            for (int nt = 0; nt < 4; nt++)
                mma_bf16(acc[mt][nt], af[mt],
                         bh[nt >> 1][(nt & 1) * 2], bh[nt >> 1][(nt & 1) * 2 + 1]);
#pragma unroll
        for (int mt = 0; mt < 4; mt++)
#pragma unroll
            for (int nt = 0; nt < 4; nt++)
                mma_bf16(acc[mt][nt], af[mt],
                         bl[nt >> 1][(nt & 1) * 2], bl[nt >> 1][(nt & 1) * 2 + 1]);
#pragma unroll
        for (int mt = 0; mt < 4; mt++) {
            int row = warp_m * 64 + mt * 16 + (lane & 15);
            int seg = ks * 2 + (lane >> 4);
            ldm_x4(af[mt], sb + 16384 + SW128(row * 128 + seg * 16));
        }
#pragma unroll
        for (int mt = 0; mt < 4; mt++)
#pragma unroll
            for (int nt = 0; nt < 4; nt++)
                mma_bf16(acc[mt][nt], af[mt],
                         bh[nt >> 1][(nt & 1) * 2], bh[nt >> 1][(nt & 1) * 2 + 1]);
    }

    const int mrow = lane >> 2;
    const int ncol = 2 * (lane & 3);
#pragma unroll
    for (int mt = 0; mt < 4; mt++)
#pragma unroll
        for (int nt = 0; nt < 4; nt++) {
            int cg = c0 + warp_n * 32 + nt * 8 + ncol;
#pragma unroll
            for (int half = 0; half < 2; half++) {
                int q = q0 + warp_m * 64 + mt * 16 + mrow + half * 8;
                float2 v = {acc[mt][nt][half * 2] * 0.125f,
                            acc[mt][nt][half * 2 + 1] * 0.125f};
                *(float2*)&Arow[(size_t)q * S_LEN + cg] = v;
            }
        }
}

// ---------------------------------------------------------------------------
// Row-wise causal softmax. Writes fp32 probs in place, clipped to the 128-row
// tile's k boundary (scores' idle CTAs own k >= tile_kend; masked-within-tile
// entries are written as exact zeros). No bf16 planes — av reads fp32 probs.
// ---------------------------------------------------------------------------
__global__ __launch_bounds__(256) void softmax_kernel(float* __restrict__ attn)
{
    const int q = blockIdx.x, bh = blockIdx.y;
    const size_t rbase = ((size_t)bh * S_LEN + q) * S_LEN;
    float* row = attn + rbase;
    const int tid = threadIdx.x;
    const int valid = q + 1;
    const int tile_kend = (q & ~127) + 128;
    const int b0 = 4 * tid, b1 = 4 * (tid + 256);

    float4 v0 = {-INFINITY, -INFINITY, -INFINITY, -INFINITY}, v1 = v0;
    if (b0 < valid) v0 = *(const float4*)&row[b0];
    if (b1 < valid) v1 = *(const float4*)&row[b1];
    float vals[8] = {v0.x, v0.y, v0.z, v0.w, v1.x, v1.y, v1.z, v1.w};

    float mx = -INFINITY;
#pragma unroll
    for (int i = 0; i < 8; i++) {
        int k = (i < 4) ? (b0 + i) : (b1 + i - 4);
        if (k >= valid) vals[i] = -INFINITY;
        mx = fmaxf(mx, vals[i]);
    }
#pragma unroll
    for (int o = 16; o; o >>= 1) mx = fmaxf(mx, __shfl_xor_sync(~0u, mx, o));
    __shared__ float sred[8];
    if ((tid & 31) == 0) sred[tid >> 5] = mx;
    __syncthreads();
    mx = sred[0];
#pragma unroll
    for (int i = 1; i < 8; i++) mx = fmaxf(mx, sred[i]);
    __syncthreads();

    float sum = 0.f;
#pragma unroll
    for (int i = 0; i < 8; i++) {
        float e = __expf(vals[i] - mx);
        vals[i] = e;
        sum += e;
    }
#pragma unroll
    for (int o = 16; o; o >>= 1) sum += __shfl_xor_sync(~0u, sum, o);
    if ((tid & 31) == 0) sred[tid >> 5] = sum;
    __syncthreads();
    sum = 0.f;
#pragma unroll
    for (int i = 0; i < 8; i++) sum += sred[i];
    const float inv = 1.f / sum;

    if (b0 < tile_kend) {
        float4 w0 = {vals[0] * inv, vals[1] * inv, vals[2] * inv, vals[3] * inv};
        *(float4*)&row[b0] = w0;
    }
    if (b1 < tile_kend) {
        float4 w1 = {vals[4] * inv, vals[5] * inv, vals[6] * inv, vals[7] * inv};
        *(float4*)&row[b1] = w1;
    }
}

// ---------------------------------------------------------------------------
// av_mma: A[q,hd] = Ph*Vh + Pl*Vh + Ph*Vl.  P read as fp32 probs from the attn
// output (LDG prefetch -> in-register bf16 hi/lo split -> STS), V via cp.async.
// Causal chunk bound; 2 CTAs/SM. Writes A in [hi|lo]-interleaved layout.
// Stage: Ph@0, Pl@16K, Vh@32K, Vl@40K (48K/stage, 2 stages).
// ---------------------------------------------------------------------------
#define AV_SMEM 98304

__global__ void __launch_bounds__(256, 2) av_mma(
    const float* __restrict__ Pf,
    const __nv_bfloat16* __restrict__ Vth, const __nv_bfloat16* __restrict__ Vtl,
    __nv_bfloat16* __restrict__ Acat)
{
    const int qt = blockIdx.x, bh = blockIdx.y;
    extern __shared__ __align__(1024) char smem[];
    const int tid = threadIdx.x;
    const int wid = tid >> 5, lane = tid & 31;
    const int warp_m = wid & 3;
    const int warp_n = wid >> 2;
    const uint32_t sb = smem_u32(smem);
    const int q0 = qt * 128;

    const float* Pb = Pf + (size_t)bh * S_LEN * S_LEN;
    const __nv_bfloat16* Vhb = Vth + (size_t)bh * HD * S_LEN;
    const __nv_bfloat16* Vlb = Vtl + (size_t)bh * HD * S_LEN;

    const int ls = tid & 7;
    const int lr = tid >> 3;
    const int prow = tid >> 1;          // P row 0..127
    const int pc0 = (tid & 1) * 32;     // P col start (32 floats per thread)
    const int nch = (q0 + 128) / 64;

    float4 pf[8];

#define LDG_P(chunk) do {                                                      \
        const float* src_ = Pb + (size_t)(q0 + prow) * S_LEN + (chunk) * 64 + pc0; \
        _Pragma("unroll")                                                      \
        for (int j_ = 0; j_ < 8; j_++)                                         \
            pf[j_] = __ldg((const float4*)(src_ + j_ * 4));                    \
    } while (0)

#define CONV_P(stage) do {                                                     \
        char* ph_ = smem + (stage) * 49152;                                    \
        _Pragma("unroll")                                                      \
        for (int j_ = 0; j_ < 8; j_++) {                                       \
            float p0_ = pf[j_].x, p1_ = pf[j_].y, p2_ = pf[j_].z, p3_ = pf[j_].w; \
            __nv_bfloat16 h0_ = __float2bfloat16(p0_);                         \
            __nv_bfloat16 h1_ = __float2bfloat16(p1_);                         \
            __nv_bfloat16 h2_ = __float2bfloat16(p2_);                         \
            __nv_bfloat16 h3_ = __float2bfloat16(p3_);                         \
            __nv_bfloat16 l0_ = __float2bfloat16(p0_ - __bfloat162float(h0_)); \
            __nv_bfloat16 l1_ = __float2bfloat16(p1_ - __bfloat162float(h1_)); \
            __nv_bfloat16 l2_ = __float2bfloat16(p2_ - __bfloat162float(h2_)); \
            __nv_bfloat16 l3_ = __float2bfloat16(p3_ - __bfloat162float(h3_)); \
            __nv_bfloat162 H01_ = __halves2bfloat162(h0_, h1_);                \
            __nv_bfloat162 H23_ = __halves2bfloat162(h2_, h3_);                \
            __nv_bfloat162 L01_ = __halves2bfloat162(l0_, l1_);                \
            __nv_bfloat162 L23_ = __halves2bfloat162(l2_, l3_);                \
            uint32_t off_ = SW128(prow * 128 + (pc0 + j_ * 4) * 2);            \
            uint2 Hp_, Lp_;                                                    \
            Hp_.x = *(uint32_t*)&H01_; Hp_.y = *(uint32_t*)&H23_;              \
            Lp_.x = *(uint32_t*)&L01_; Lp_.y = *(uint32_t*)&L23_;              \
            *(uint2*)(ph_ + off_) = Hp_;                                       \
            *(uint2*)(ph_ + 16384 + off_) = Lp_;                               \
        }                                                                      \
    } while (0)

#define LOADV(chunk, stage) do {                                               \
        uint32_t base_ = sb + (stage) * 49152;                                 \
        size_t kb_ = (size_t)(chunk) * 64 + ls * 8;                            \
        _Pragma("unroll")                                                      \
        for (int i_ = 0; i_ < 2; i_++) {                                       \
            int r_ = lr + 32 * i_;                                             \
            uint32_t off_ = SW128(r_ * 128 + ls * 16);                         \
            CP16(base_ + 32768 + off_, &Vhb[(size_t)r_ * S_LEN + kb_]);        \
            CP16(base_ + 40960 + off_, &Vlb[(size_t)r_ * S_LEN + kb_]);        \
        }                                                                      \
        CP_COMMIT();                                                           \
    } while (0)

    // prologue: P chunk 0 convert + V chunks 0,1 in flight, P chunk 1 in regs
    LDG_P(0);
    LOADV(0, 0);
    CONV_P(0);
    if (nch > 1) { LDG_P(1); LOADV(1, 1); }

    float acc[2][4][4] = {};
    for (int c = 0; c < nch; c++) {
        const int st = c & 1;
        if (c + 1 < nch) asm volatile("cp.async.wait_group 1;");
        else             asm volatile("cp.async.wait_group 0;");
        __syncthreads();   // V chunk c arrived; P chunk c STS visible

        const uint32_t base = sb + st * 49152;
#pragma unroll
        for (int ks = 0; ks < 4; ks++) {
            uint32_t ah[2][4], al[2][4];
#pragma unroll
            for (int mt = 0; mt < 2; mt++) {
                int row = warp_m * 32 + mt * 16 + (lane & 15);
                int seg = ks * 2 + (lane >> 4);
                uint32_t off = SW128(row * 128 + seg * 16);
                ldm_x4(ah[mt], base + off);
                ldm_x4(al[mt], base + 16384 + off);
            }
            uint32_t bh_[2][4], bl_[2][4];
#pragma unroll
            for (int h = 0; h < 2; h++) {
                int row = warp_n * 32 + h * 16 + ((lane >> 4) & 1) * 8 + (lane & 7);
                int seg = ks * 2 + ((lane >> 3) & 1);
                uint32_t off = SW128(row * 128 + seg * 16);
                ldm_x4(bh_[h], base + 32768 + off);
                ldm_x4(bl_[h], base + 40960 + off);
            }
#pragma unroll
            for (int mt = 0; mt < 2; mt++)
#pragma unroll
                for (int nt = 0; nt < 4; nt++) {
                    uint32_t vh0 = bh_[nt >> 1][(nt & 1) * 2];
                    uint32_t vh1 = bh_[nt >> 1][(nt & 1) * 2 + 1];
                    uint32_t vl0 = bl_[nt >> 1][(nt & 1) * 2];
                    uint32_t vl1 = bl_[nt >> 1][(nt & 1) * 2 + 1];
                    mma_bf16(acc[mt][nt], ah[mt], vh0, vh1);
                    mma_bf16(acc[mt][nt], al[mt], vh0, vh1);
                    mma_bf16(acc[mt][nt], ah[mt], vl0, vl1);
                }
        }

        // convert P chunk c+1 (in regs) into the other stage; disjoint from
        // the regions read above, so no barrier needed before the STS.
        if (c + 1 < nch) CONV_P(st ^ 1);
        __syncthreads();   // all warps done with stage st (mma) + STS visible
        if (c + 2 < nch) { LDG_P(c + 2); LOADV(c + 2, st); }
    }
#undef LDG_P
#undef CONV_P
#undef LOADV

    const int bb = bh / NH, h = bh % NH;
    const int mrow = lane >> 2;
    const int ncol = 2 * (lane & 3);
#pragma unroll
    for (int mt = 0; mt < 2; mt++)
#pragma unroll
        for (int nt = 0; nt < 4; nt++) {
            int hd = warp_n * 32 + nt * 8 + ncol;
            int cc = h * HD + hd;
            int ch = cc >> 5, p = cc & 31;
#pragma unroll
            for (int half = 0; half < 2; half++) {
                int s = q0 + warp_m * 32 + mt * 16 + mrow + half * 8;
                float v0 = acc[mt][nt][half * 2];
                float v1 = acc[mt][nt][half * 2 + 1];
                __nv_bfloat16 h0 = __float2bfloat16(v0);
                __nv_bfloat16 h1 = __float2bfloat16(v1);
                __nv_bfloat16 l0 = __float2bfloat16(v0 - __bfloat162float(h0));
                __nv_bfloat16 l1 = __float2bfloat16(v1 - __bfloat162float(h1));
                size_t base = ((size_t)(bb * S_LEN + s)) * KC2 + ch * 64 + p;
                *(__nv_bfloat162*)&Acat[base]      = __halves2bfloat162(h0, h1);
                *(__nv_bfloat162*)&Acat[base + 32] = __halves2bfloat162(l0, l1);
            }
        }
}

// ---------------------------------------------------------------------------
extern "C" void kernel_launch(void* const* d_in, const int* in_sizes, int n_in,
                              void* d_out, int out_size)
{
    const float* X  = (const float*)d_in[0];
    const float* Wq = (const float*)d_in[1];
    const float* bq = (const float*)d_in[2];
    const float* Wk = (const float*)d_in[3];
    const float* bk = (const float*)d_in[4];
    const float* Wv = (const float*)d_in[5];
    const float* bv = (const float*)d_in[6];
    const float* Wo = (const float*)d_in[7];
    const float* bo = (const float*)d_in[8];

    float* out  = (float*)d_out;
    float* attn = out + (size_t)MROWS * DM;

    __nv_bfloat16 *gXc, *gAc, *gWq, *gWk, *gWv, *gWo;
    __nv_bfloat16 *gQc, *gKc, *gVh, *gVl;
    cudaGetSymbolAddress((void**)&gXc, g_Xcat);
    cudaGetSymbolAddress((void**)&gAc, g_Acat);
    cudaGetSymbolAddress((void**)&gWq, g_Wqc);
    cudaGetSymbolAddress((void**)&gWk, g_Wkc);
    cudaGetSymbolAddress((void**)&gWv, g_Wvc);
    cudaGetSymbolAddress((void**)&gWo, g_Woc);
    cudaGetSymbolAddress((void**)&gQc, g_Qc);
    cudaGetSymbolAddress((void**)&gKc, g_Kc);
    cudaGetSymbolAddress((void**)&gVh, g_Vth);
    cudaGetSymbolAddress((void**)&gVl, g_Vtl);

    static cudaStream_t s1, s2, s3;
    static cudaEvent_t evRoot, evX, ev1, ev2, ev3;
    static int init_done = 0;
    if (!init_done) {
        cudaFuncSetAttribute(gemm_mma, cudaFuncAttributeMaxDynamicSharedMemorySize, GEMM_SMEM);
        cudaFuncSetAttribute(scores_mma, cudaFuncAttributeMaxDynamicSharedMemorySize, SC_SMEM);
        cudaFuncSetAttribute(av_mma, cudaFuncAttributeMaxDynamicSharedMemorySize, AV_SMEM);
        cudaStreamCreateWithFlags(&s1, cudaStreamNonBlocking);
        cudaStreamCreateWithFlags(&s2, cudaStreamNonBlocking);
        cudaStreamCreateWithFlags(&s3, cudaStreamNonBlocking);
        cudaEventCreateWithFlags(&evRoot, cudaEventDisableTiming);
        cudaEventCreateWithFlags(&evX, cudaEventDisableTiming);
        cudaEventCreateWithFlags(&ev1, cudaEventDisableTiming);
        cudaEventCreateWithFlags(&ev2, cudaEventDisableTiming);
        cudaEventCreateWithFlags(&ev3, cudaEventDisableTiming);
        init_done = 1;
    }

    dim3 blk(256);
    dim3 ggemm(DM / 128, MROWS / 128);

    cudaEventRecord(evRoot, 0);
    cudaStreamWaitEvent(s1, evRoot, 0);
    cudaStreamWaitEvent(s2, evRoot, 0);
    cudaStreamWaitEvent(s3, evRoot, 0);

    convert_cat<<<1024, blk, 0, 0>>>(X, gXc, MROWS);
    cudaEventRecord(evX, 0);
    convert_cat<<<512, blk, 0, 0>>>(Wo, gWo, DM);

    convert_cat<<<512, blk, 0, s1>>>(Wq, gWq, DM);
    cudaStreamWaitEvent(s1, evX, 0);
    gemm_mma<<<ggemm, blk, GEMM_SMEM, s1>>>(gXc, gWq, bq, nullptr, gQc, nullptr, 1);
    cudaEventRecord(ev1, s1);

    convert_cat<<<512, blk, 0, s2>>>(Wk, gWk, DM);
    cudaStreamWaitEvent(s2, evX, 0);
    gemm_mma<<<ggemm, blk, GEMM_SMEM, s2>>>(gXc, gWk, bk, nullptr, gKc, nullptr, 1);
    cudaEventRecord(ev2, s2);

    convert_cat<<<512, blk, 0, s3>>>(Wv, gWv, DM);
    cudaStreamWaitEvent(s3, evX, 0);
    gemm_mma<<<ggemm, blk, GEMM_SMEM, s3>>>(gXc, gWv, bv, nullptr, gVh, gVl, 3);
    cudaEventRecord(ev3, s3);

    cudaStreamWaitEvent(0, ev1, 0);
    cudaStreamWaitEvent(0, ev2, 0);
    dim3 gsc(S_LEN / 128, S_LEN / 128, BHN);
    scores_mma<<<gsc, blk, SC_SMEM, 0>>>(gQc, gKc, attn);

    dim3 gsm(S_LEN, BHN);
    softmax_kernel<<<gsm, blk, 0, 0>>>(attn);

    cudaStreamWaitEvent(0, ev3, 0);
    dim3 gav(S_LEN / 128, BHN);
    av_mma<<<gav, blk, AV_SMEM, 0>>>(attn, gVh, gVl, gAc);

    gemm_mma<<<ggemm, blk, GEMM_SMEM, 0>>>(gAc, gWo, bo, out, nullptr, nullptr, 0);
}

// round 13
// speedup vs baseline: 1.1006x; 1.1006x over previous
#include <cuda_runtime.h>
#include <cuda_bf16.h>
#include <math.h>
#include <stdint.h>

#define S_LEN 2048
#define DM    1024
#define NH    16
#define HD    64
#define BATCH 2
#define BHN   (BATCH * NH)        // 32
#define MROWS (BATCH * S_LEN)     // 4096
#define KC2   2048                // [hi|lo] interleaved per 32-k chunk
#define NCH2  32                  // 32 chunks of 32 k-elems
#define QK2   128                 // Q/K row: [hi 64 | lo 64]

// ---------------- scratch (__device__ globals) ------------------------------
__device__ __nv_bfloat16 g_Xcat[(size_t)MROWS * KC2];
__device__ __nv_bfloat16 g_Acat[(size_t)MROWS * KC2];
__device__ __nv_bfloat16 g_Wqc[(size_t)DM * KC2];
__device__ __nv_bfloat16 g_Wkc[(size_t)DM * KC2];
__device__ __nv_bfloat16 g_Wvc[(size_t)DM * KC2];
__device__ __nv_bfloat16 g_Woc[(size_t)DM * KC2];
__device__ __nv_bfloat16 g_Qc[(size_t)BHN * S_LEN * QK2];   // [hi|lo]
__device__ __nv_bfloat16 g_Kc[(size_t)BHN * S_LEN * QK2];   // [hi|lo]
__device__ __nv_bfloat16 g_Vth[(size_t)BHN * HD * S_LEN];   // V^T hi
__device__ __nv_bfloat16 g_Vtl[(size_t)BHN * HD * S_LEN];   // V^T lo
__device__ __nv_bfloat16 g_Ph[(size_t)BHN * S_LEN * S_LEN]; // P hi
__device__ __nv_bfloat16 g_Pl[(size_t)BHN * S_LEN * S_LEN]; // P lo

// ---------------- helpers ---------------------------------------------------
__device__ __forceinline__ uint32_t smem_u32(const void* p) {
    uint32_t a;
    asm("{ .reg .u64 t; cvta.to.shared.u64 t, %1; cvt.u32.u64 %0, t; }"
        : "=r"(a) : "l"(p));
    return a;
}
#define SW128(o) ((o) ^ (((o) >> 3) & 0x70))

__device__ __forceinline__ void ldm_x4(uint32_t* r, uint32_t addr) {
    asm volatile("ldmatrix.sync.aligned.m8n8.x4.shared.b16 {%0,%1,%2,%3}, [%4];"
                 : "=r"(r[0]), "=r"(r[1]), "=r"(r[2]), "=r"(r[3]) : "r"(addr));
}
__device__ __forceinline__ void mma_bf16(float* c, const uint32_t* a,
                                         uint32_t b0, uint32_t b1) {
    asm volatile(
        "mma.sync.aligned.m16n8k16.row.col.f32.bf16.bf16.f32 "
        "{%0,%1,%2,%3}, {%4,%5,%6,%7}, {%8,%9}, {%0,%1,%2,%3};"
        : "+f"(c[0]), "+f"(c[1]), "+f"(c[2]), "+f"(c[3])
        : "r"(a[0]), "r"(a[1]), "r"(a[2]), "r"(a[3]), "r"(b0), "r"(b1));
}
#define CP16(dst, src) \
    asm volatile("cp.async.cg.shared.global [%0], [%1], 16;" :: "r"(dst), "l"(src))
#define CP_COMMIT() asm volatile("cp.async.commit_group;")

// ---------------------------------------------------------------------------
// fp32 [rows,1024] -> bf16 [rows,2048], per-32-chunk interleave [hi32|lo32].
// ---------------------------------------------------------------------------
__device__ __forceinline__ void conv_body(
    const float* __restrict__ src, __nv_bfloat16* __restrict__ dst,
    int rows, int gid, int gstride)
{
    int n = rows * (DM / 4);
    for (int i = gid; i < n; i += gstride) {
        int r = i / (DM / 4), cq = i - r * (DM / 4);
        float4 v = *(const float4*)&src[(size_t)r * DM + cq * 4];
        float f[4] = {v.x, v.y, v.z, v.w};
        __nv_bfloat16 hi[4], lo[4];
#pragma unroll
        for (int j = 0; j < 4; j++) {
            hi[j] = __float2bfloat16(f[j]);
            lo[j] = __float2bfloat16(f[j] - __bfloat162float(hi[j]));
        }
        int c = cq >> 3;
        int p = (cq & 7) * 4;
        size_t base = (size_t)r * KC2 + c * 64 + p;
        *(__nv_bfloat162*)&dst[base]      = __halves2bfloat162(hi[0], hi[1]);
        *(__nv_bfloat162*)&dst[base + 2]  = __halves2bfloat162(hi[2], hi[3]);
        *(__nv_bfloat162*)&dst[base + 32] = __halves2bfloat162(lo[0], lo[1]);
        *(__nv_bfloat162*)&dst[base + 34] = __halves2bfloat162(lo[2], lo[3]);
    }
}

__global__ __launch_bounds__(256) void convert_cat(
    const float* __restrict__ src, __nv_bfloat16* __restrict__ dst, int rows)
{
    conv_body(src, dst, rows, blockIdx.x * blockDim.x + threadIdx.x,
              gridDim.x * blockDim.x);
}

// all four weights in one launch: gridDim.y selects which
__global__ __launch_bounds__(256) void convert_w4(
    const float* __restrict__ w0, const float* __restrict__ w1,
    const float* __restrict__ w2, const float* __restrict__ w3,
    __nv_bfloat16* __restrict__ d0, __nv_bfloat16* __restrict__ d1,
    __nv_bfloat16* __restrict__ d2, __nv_bfloat16* __restrict__ d3)
{
    const float* src = (blockIdx.y == 0) ? w0 : (blockIdx.y == 1) ? w1
                     : (blockIdx.y == 2) ? w2 : w3;
    __nv_bfloat16* dst = (blockIdx.y == 0) ? d0 : (blockIdx.y == 1) ? d1
                       : (blockIdx.y == 2) ? d2 : d3;
    conv_body(src, dst, DM, blockIdx.x * blockDim.x + threadIdx.x,
              gridDim.x * blockDim.x);
}

// ---------------------------------------------------------------------------
// GEMM mainloop (shared by gemm_qkv and gemm_mma): 3-stage cp.async, single
// barrier per chunk (wait -> sync -> issue next load -> compute).
// ---------------------------------------------------------------------------
#define GEMM_SMEM 98304   // A: 3x16K at 0, B: 3x16K at 49152

#define GEMM_MAIN(Aptr, Bptr)                                                  \
    float acc[4][4][4] = {};                                                   \
    {                                                                          \
        /* prologue loads for chunks 0,1 */                                    \
        _Pragma("unroll")                                                      \
        for (int pc = 0; pc < 2; pc++) {                                       \
            uint32_t ab = sb + pc * 16384;                                     \
            uint32_t bb = sb + 49152 + pc * 16384;                             \
            size_t kb = (size_t)pc * 64 + ls * 8;                              \
            _Pragma("unroll")                                                  \
            for (int i_ = 0; i_ < 4; i_++) {                                   \
                int r_ = lr + 32 * i_;                                         \
                uint32_t off = SW128(r_ * 128 + ls * 16);                      \
                CP16(ab + off, &Aptr[(size_t)(r0 + r_) * KC2 + kb]);           \
                CP16(bb + off, &Bptr[(size_t)(c0 + r_) * KC2 + kb]);           \
            }                                                                  \
            CP_COMMIT();                                                       \
        }                                                                      \
    }                                                                          \
    int st = 0, st2 = 2;                                                       \
    for (int c = 0; c < NCH2; c++) {                                           \
        if (c + 2 < NCH2) asm volatile("cp.async.wait_group 1;");              \
        else              asm volatile("cp.async.wait_group 0;");              \
        __syncthreads();                                                       \
        if (c + 2 < NCH2) {                                                    \
            uint32_t ab = sb + st2 * 16384;                                    \
            uint32_t bb = sb + 49152 + st2 * 16384;                            \
            size_t kb = (size_t)(c + 2) * 64 + ls * 8;                         \
            _Pragma("unroll")                                                  \
            for (int i_ = 0; i_ < 4; i_++) {                                   \
                int r_ = lr + 32 * i_;                                         \
                uint32_t off = SW128(r_ * 128 + ls * 16);                      \
                CP16(ab + off, &Aptr[(size_t)(r0 + r_) * KC2 + kb]);           \
                CP16(bb + off, &Bptr[(size_t)(c0 + r_) * KC2 + kb]);           \
            }                                                                  \
            CP_COMMIT();                                                       \
        }                                                                      \
        const uint32_t abase = sb + st * 16384;                                \
        const uint32_t bbase = sb + 49152 + st * 16384;                        \
        _Pragma("unroll")                                                      \
        for (int ks = 0; ks < 2; ks++) {                                       \
            uint32_t af[4][4];                                                 \
            uint32_t bhf[2][4], blf[2][4];                                     \
            _Pragma("unroll")                                                  \
            for (int mt = 0; mt < 4; mt++) {                                   \
                int row = warp_m * 64 + mt * 16 + (lane & 15);                 \
                int seg = ks * 2 + (lane >> 4);                                \
                ldm_x4(af[mt], abase + SW128(row * 128 + seg * 16));           \
            }                                                                  \
            _Pragma("unroll")                                                  \
            for (int h = 0; h < 2; h++) {                                      \
                int row = warp_n * 32 + h * 16 + ((lane >> 4) & 1) * 8 + (lane & 7); \
                int seg = ks * 2 + ((lane >> 3) & 1);                          \
                uint32_t off = row * 128 + seg * 16;                           \
                ldm_x4(bhf[h], bbase + SW128(off));                            \
                ldm_x4(blf[h], bbase + SW128(off + 64));                       \
            }                                                                  \
            _Pragma("unroll")                                                  \
            for (int mt = 0; mt < 4; mt++)                                     \
                _Pragma("unroll")                                              \
                for (int nt = 0; nt < 4; nt++)                                 \
                    mma_bf16(acc[mt][nt], af[mt],                              \
                             bhf[nt >> 1][(nt & 1) * 2], bhf[nt >> 1][(nt & 1) * 2 + 1]); \
            _Pragma("unroll")                                                  \
            for (int mt = 0; mt < 4; mt++)                                     \
                _Pragma("unroll")                                              \
                for (int nt = 0; nt < 4; nt++)                                 \
                    mma_bf16(acc[mt][nt], af[mt],                              \
                             blf[nt >> 1][(nt & 1) * 2], blf[nt >> 1][(nt & 1) * 2 + 1]); \
            _Pragma("unroll")                                                  \
            for (int mt = 0; mt < 4; mt++) {                                   \
                int row = warp_m * 64 + mt * 16 + (lane & 15);                 \
                int seg = 4 + ks * 2 + (lane >> 4);                            \
                ldm_x4(af[mt], abase + SW128(row * 128 + seg * 16));           \
            }                                                                  \
            _Pragma("unroll")                                                  \
            for (int mt = 0; mt < 4; mt++)                                     \
                _Pragma("unroll")                                              \
                for (int nt = 0; nt < 4; nt++)                                 \
                    mma_bf16(acc[mt][nt], af[mt],                              \
                             bhf[nt >> 1][(nt & 1) * 2], bhf[nt >> 1][(nt & 1) * 2 + 1]); \
        }                                                                      \
        st  = (st  == 2) ? 0 : st + 1;                                         \
        st2 = (st2 == 2) ? 0 : st2 + 1;                                        \
    }

// ---------------------------------------------------------------------------
// gemm_qkv: one launch for Q, K, V projections (blockIdx.z selects operand).
// z=0 -> Q [hi|lo]; z=1 -> K [hi|lo]; z=2 -> V^T hi/lo planes.
// ---------------------------------------------------------------------------
__global__ void __launch_bounds__(256, 2) gemm_qkv(
    const __nv_bfloat16* __restrict__ A,
    const __nv_bfloat16* __restrict__ Bq, const __nv_bfloat16* __restrict__ Bk,
    const __nv_bfloat16* __restrict__ Bv,
    const float* __restrict__ bq, const float* __restrict__ bk,
    const float* __restrict__ bv,
    __nv_bfloat16* __restrict__ oQ, __nv_bfloat16* __restrict__ oK,
    __nv_bfloat16* __restrict__ oVh, __nv_bfloat16* __restrict__ oVl)
{
    extern __shared__ __align__(1024) char smem[];
    const int z = blockIdx.z;
    const __nv_bfloat16* B = (z == 0) ? Bq : (z == 1) ? Bk : Bv;
    const float* bias = (z == 0) ? bq : (z == 1) ? bk : bv;

    const int tid = threadIdx.x;
    const int wid = tid >> 5, lane = tid & 31;
    const int warp_m = wid >> 2;
    const int warp_n = wid & 3;
    const uint32_t sb = smem_u32(smem);
    const int r0 = blockIdx.y * 128, c0 = blockIdx.x * 128;
    const int ls = tid & 7;
    const int lr = tid >> 3;

    GEMM_MAIN(A, B)

    const int mrow = lane >> 2;
    const int ncol = 2 * (lane & 3);
#pragma unroll
    for (int mt = 0; mt < 4; mt++) {
#pragma unroll
        for (int nt = 0; nt < 4; nt++) {
            int cg = c0 + warp_n * 32 + nt * 8 + ncol;
            float b0 = __ldg(&bias[cg]), b1 = __ldg(&bias[cg + 1]);
#pragma unroll
            for (int half = 0; half < 2; half++) {
                int r = r0 + warp_m * 64 + mt * 16 + mrow + half * 8;
                float v0 = acc[mt][nt][half * 2] + b0;
                float v1 = acc[mt][nt][half * 2 + 1] + b1;
                int bb = r >> 11, s = r & (S_LEN - 1);
                int h = cg >> 6, hd = cg & 63;
                __nv_bfloat16 h0 = __float2bfloat16(v0);
                __nv_bfloat16 h1 = __float2bfloat16(v1);
                __nv_bfloat16 l0 = __float2bfloat16(v0 - __bfloat162float(h0));
                __nv_bfloat16 l1 = __float2bfloat16(v1 - __bfloat162float(h1));
                if (z == 2) {
                    size_t pb = ((size_t)(bb * NH + h) * HD + hd) * S_LEN + s;
                    oVh[pb] = h0; oVh[pb + S_LEN] = h1;
                    oVl[pb] = l0; oVl[pb + S_LEN] = l1;
                } else {
                    __nv_bfloat16* ob = (z == 0) ? oQ : oK;
                    size_t base = ((size_t)(bb * NH + h) * S_LEN + s) * QK2 + hd;
                    *(__nv_bfloat162*)&ob[base]      = __halves2bfloat162(h0, h1);
                    *(__nv_bfloat162*)&ob[base + 64] = __halves2bfloat162(l0, l1);
                }
            }
        }
    }
}

// ---------------------------------------------------------------------------
// gemm_mma: Wo projection, fp32 row-major output.
// ---------------------------------------------------------------------------
__global__ void __launch_bounds__(256, 2) gemm_mma(
    const __nv_bfloat16* __restrict__ A, const __nv_bfloat16* __restrict__ B,
    const float* __restrict__ bias, float* __restrict__ outf)
{
    extern __shared__ __align__(1024) char smem[];
    const int tid = threadIdx.x;
    const int wid = tid >> 5, lane = tid & 31;
    const int warp_m = wid >> 2;
    const int warp_n = wid & 3;
    const uint32_t sb = smem_u32(smem);
    const int r0 = blockIdx.y * 128, c0 = blockIdx.x * 128;
    const int ls = tid & 7;
    const int lr = tid >> 3;

    GEMM_MAIN(A, B)

    const int mrow = lane >> 2;
    const int ncol = 2 * (lane & 3);
#pragma unroll
    for (int mt = 0; mt < 4; mt++) {
#pragma unroll
        for (int nt = 0; nt < 4; nt++) {
            int cg = c0 + warp_n * 32 + nt * 8 + ncol;
            float b0 = __ldg(&bias[cg]), b1 = __ldg(&bias[cg + 1]);
#pragma unroll
            for (int half = 0; half < 2; half++) {
                int r = r0 + warp_m * 64 + mt * 16 + mrow + half * 8;
                float2 v = {acc[mt][nt][half * 2] + b0,
                            acc[mt][nt][half * 2 + 1] + b1};
                *(float2*)&outf[(size_t)r * DM + cg] = v;
            }
        }
    }
}

// ---------------------------------------------------------------------------
// scores_mma: attn = 0.125 * (Qh*Kh + Qh*Kl + Ql*Kh).  Q/K rows [hi|lo] (128).
// Upper-triangle CTAs (kt > qt) zero-fill their attn tile instead of exiting.
// ---------------------------------------------------------------------------
#define SC_SMEM 65536

__global__ __launch_bounds__(256) void scores_mma(
    const __nv_bfloat16* __restrict__ Qc, const __nv_bfloat16* __restrict__ Kc,
    float* __restrict__ attn)
{
    const int kt = blockIdx.x, qt = blockIdx.y, bh = blockIdx.z;
    const int q0 = qt * 128, c0 = kt * 128;
    float* Arow = attn + (size_t)bh * S_LEN * S_LEN;

    if (kt > qt) {
        const float4 z = {0.f, 0.f, 0.f, 0.f};
        const int tid = threadIdx.x;
        for (int idx = tid; idx < 128 * 32; idx += 256) {
            int r = idx >> 5, c = (idx & 31) * 4;
            *(float4*)&Arow[(size_t)(q0 + r) * S_LEN + c0 + c] = z;
        }
        return;
    }

    extern __shared__ __align__(1024) char smem[];
    const int tid = threadIdx.x;
    const int wid = tid >> 5, lane = tid & 31;
    const int warp_m = wid >> 2;
    const int warp_n = wid & 3;
    const uint32_t sb = smem_u32(smem);

    const __nv_bfloat16* Qb = Qc + (size_t)bh * S_LEN * QK2;
    const __nv_bfloat16* Kb = Kc + (size_t)bh * S_LEN * QK2;
    const int ls = tid & 7;
    const int lr = tid >> 3;

#pragma unroll
    for (int i_ = 0; i_ < 4; i_++) {
        int r_ = lr + 32 * i_;
        uint32_t off = SW128(r_ * 128 + ls * 16);
        CP16(sb + off,         &Qb[(size_t)(q0 + r_) * QK2 + ls * 8]);
        CP16(sb + 16384 + off, &Qb[(size_t)(q0 + r_) * QK2 + 64 + ls * 8]);
        CP16(sb + 32768 + off, &Kb[(size_t)(c0 + r_) * QK2 + ls * 8]);
        CP16(sb + 49152 + off, &Kb[(size_t)(c0 + r_) * QK2 + 64 + ls * 8]);
    }
    CP_COMMIT();
    asm volatile("cp.async.wait_group 0;");
    __syncthreads();

    float acc[4][4][4] = {};
#pragma unroll
    for (int ks = 0; ks < 4; ks++) {
        uint32_t af[4][4], bh[2][4], bl[2][4];
#pragma unroll
        for (int mt = 0; mt < 4; mt++) {
            int row = warp_m * 64 + mt * 16 + (lane & 15);
            int seg = ks * 2 + (lane >> 4);
            ldm_x4(af[mt], sb + SW128(row * 128 + seg * 16));
        }
#pragma unroll
        for (int h = 0; h < 2; h++) {
            int row = warp_n * 32 + h * 16 + ((lane >> 4) & 1) * 8 + (lane & 7);
            int seg = ks * 2 + ((lane >> 3) & 1);
            uint32_t off = SW128(row * 128 + seg * 16);
            ldm_x4(bh[h], sb + 32768 + off);
            ldm_x4(bl[h], sb + 49152 + off);
        }
#pragma unroll
        for (int mt = 0; mt < 4; mt++)
#pragma unroll
            for (int nt = 0; nt < 4; nt++)
                mma_bf16(acc[mt][nt], af[mt],
                         bh[nt >> 1][(nt & 1) * 2], bh[nt >> 1][(nt & 1) * 2 + 1]);
#pragma unroll
        for (int mt = 0; mt < 4; mt++)
#pragma unroll
            for (int nt = 0; nt < 4; nt++)
                mma_bf16(acc[mt][nt], af[mt],
                         bl[nt >> 1][(nt & 1) * 2], bl[nt >> 1][(nt & 1) * 2 + 1]);
#pragma unroll
        for (int mt = 0; mt < 4; mt++) {
            int row = warp_m * 64 + mt * 16 + (lane & 15);
            int seg = ks * 2 + (lane >> 4);
            ldm_x4(af[mt], sb + 16384 + SW128(row * 128 + seg * 16));
        }
#pragma unroll
        for (int mt = 0; mt < 4; mt++)
#pragma unroll
            for (int nt = 0; nt < 4; nt++)
                mma_bf16(acc[mt][nt], af[mt],
                         bh[nt >> 1][(nt & 1) * 2], bh[nt >> 1][(nt & 1) * 2 + 1]);
    }

    const int mrow = lane >> 2;
    const int ncol = 2 * (lane & 3);
#pragma unroll
    for (int mt = 0; mt < 4; mt++)
#pragma unroll
        for (int nt = 0; nt < 4; nt++) {
            int cg = c0 + warp_n * 32 + nt * 8 + ncol;
#pragma unroll
            for (int half = 0; half < 2; half++) {
                int q = q0 + warp_m * 64 + mt * 16 + mrow + half * 8;
                float2 v = {acc[mt][nt][half * 2] * 0.125f,
                            acc[mt][nt][half * 2 + 1] * 0.125f};
                *(float2*)&Arow[(size_t)q * S_LEN + cg] = v;
            }
        }
}

// ---------------------------------------------------------------------------
// Row-wise causal softmax. fp32 probs + bf16 hi/lo planes, clipped to the
// 128-row tile's k boundary (scores' idle CTAs own k >= tile_kend).
// ---------------------------------------------------------------------------
__global__ __launch_bounds__(256) void softmax_kernel(
    float* __restrict__ attn, __nv_bfloat16* __restrict__ Ph,
    __nv_bfloat16* __restrict__ Pl)
{
    const int q = blockIdx.x, bh = blockIdx.y;
    const size_t rbase = ((size_t)bh * S_LEN + q) * S_LEN;
    float* row = attn + rbase;
    const int tid = threadIdx.x;
    const int valid = q + 1;
    const int tile_kend = (q & ~127) + 128;
    const int b0 = 4 * tid, b1 = 4 * (tid + 256);

    float4 v0 = {-INFINITY, -INFINITY, -INFINITY, -INFINITY}, v1 = v0;
    if (b0 < valid) v0 = *(const float4*)&row[b0];
    if (b1 < valid) v1 = *(const float4*)&row[b1];
    float vals[8] = {v0.x, v0.y, v0.z, v0.w, v1.x, v1.y, v1.z, v1.w};

    float mx = -INFINITY;
#pragma unroll
    for (int i = 0; i < 8; i++) {
        int k = (i < 4) ? (b0 + i) : (b1 + i - 4);
        if (k >= valid) vals[i] = -INFINITY;
        mx = fmaxf(mx, vals[i]);
    }
#pragma unroll
    for (int o = 16; o; o >>= 1) mx = fmaxf(mx, __shfl_xor_sync(~0u, mx, o));
    __shared__ float sred[8];
    if ((tid & 31) == 0) sred[tid >> 5] = mx;
    __syncthreads();
    mx = sred[0];
#pragma unroll
    for (int i = 1; i < 8; i++) mx = fmaxf(mx, sred[i]);
    __syncthreads();

    float sum = 0.f;
#pragma unroll
    for (int i = 0; i < 8; i++) {
        float e = __expf(vals[i] - mx);
        vals[i] = e;
        sum += e;
    }
#pragma unroll
    for (int o = 16; o; o >>= 1) sum += __shfl_xor_sync(~0u, sum, o);
    if ((tid & 31) == 0) sred[tid >> 5] = sum;
    __syncthreads();
    sum = 0.f;
#pragma unroll
    for (int i = 0; i < 8; i++) sum += sred[i];
    const float inv = 1.f / sum;

    float p[8];
    __nv_bfloat16 hh[8], ll[8];
#pragma unroll
    for (int i = 0; i < 8; i++) {
        p[i] = vals[i] * inv;
        hh[i] = __float2bfloat16(p[i]);
        ll[i] = __float2bfloat16(p[i] - __bfloat162float(hh[i]));
    }
    if (b0 < tile_kend) {
        float4 w0 = {p[0], p[1], p[2], p[3]};
        *(float4*)&row[b0] = w0;
#pragma unroll
        for (int j = 0; j < 2; j++) {
            *(__nv_bfloat162*)&Ph[rbase + b0 + 2*j] = __halves2bfloat162(hh[2*j], hh[2*j+1]);
            *(__nv_bfloat162*)&Pl[rbase + b0 + 2*j] = __halves2bfloat162(ll[2*j], ll[2*j+1]);
        }
    }
    if (b1 < tile_kend) {
        float4 w1 = {p[4], p[5], p[6], p[7]};
        *(float4*)&row[b1] = w1;
#pragma unroll
        for (int j = 0; j < 2; j++) {
            *(__nv_bfloat162*)&Ph[rbase + b1 + 2*j] = __halves2bfloat162(hh[4+2*j], hh[5+2*j]);
            *(__nv_bfloat162*)&Pl[rbase + b1 + 2*j] = __halves2bfloat162(ll[4+2*j], ll[5+2*j]);
        }
    }
}

// ---------------------------------------------------------------------------
// av_mma: A[q,hd] = Ph*Vh + Pl*Vh + Ph*Vl; causal chunk bound; 2 CTAs/SM.
// Writes A in [hi|lo]-interleaved layout for the Wo GEMM.
// ---------------------------------------------------------------------------
#define AV_SMEM 98304

__global__ void __launch_bounds__(256, 2) av_mma(
    const __nv_bfloat16* __restrict__ Ph, const __nv_bfloat16* __restrict__ Pl,
    const __nv_bfloat16* __restrict__ Vth, const __nv_bfloat16* __restrict__ Vtl,
    __nv_bfloat16* __restrict__ Acat)
{
    const int qt = blockIdx.x, bh = blockIdx.y;
    extern __shared__ __align__(1024) char smem[];
    const int tid = threadIdx.x;
    const int wid = tid >> 5, lane = tid & 31;
    const int warp_m = wid & 3;
    const int warp_n = wid >> 2;
    const uint32_t sb = smem_u32(smem);
    const int q0 = qt * 128;

    const __nv_bfloat16* Phb = Ph + (size_t)bh * S_LEN * S_LEN;
    const __nv_bfloat16* Plb = Pl + (size_t)bh * S_LEN * S_LEN;
    const __nv_bfloat16* Vhb = Vth + (size_t)bh * HD * S_LEN;
    const __nv_bfloat16* Vlb = Vtl + (size_t)bh * HD * S_LEN;

    const int ls = tid & 7;
    const int lr = tid >> 3;
    const int nch = (q0 + 128) / 64;

#define AV_LOAD(chunk, stage) do {                                             \
        uint32_t base = sb + (stage) * 49152;                                  \
        size_t kb = (size_t)(chunk) * 64 + ls * 8;                             \
        _Pragma("unroll")                                                      \
        for (int i_ = 0; i_ < 4; i_++) {                                       \
            int r_ = lr + 32 * i_;                                             \
            uint32_t off = SW128(r_ * 128 + ls * 16);                          \
            CP16(base + off,         &Phb[(size_t)(q0 + r_) * S_LEN + kb]);    \
            CP16(base + 16384 + off, &Plb[(size_t)(q0 + r_) * S_LEN + kb]);    \
        }                                                                      \
        _Pragma("unroll")                                                      \
        for (int i_ = 0; i_ < 2; i_++) {                                       \
            int r_ = lr + 32 * i_;                                             \
            uint32_t off = SW128(r_ * 128 + ls * 16);                          \
            CP16(base + 32768 + off, &Vhb[(size_t)r_ * S_LEN + kb]);           \
            CP16(base + 40960 + off, &Vlb[(size_t)r_ * S_LEN + kb]);           \
        }                                                                      \
        CP_COMMIT();                                                           \
    } while (0)

    float acc[2][4][4] = {};
    AV_LOAD(0, 0);
    for (int c = 0; c < nch; c++) {
        const int st = c & 1;
        if (c + 1 < nch) {
            AV_LOAD(c + 1, st ^ 1);
            asm volatile("cp.async.wait_group 1;");
        } else {
            asm volatile("cp.async.wait_group 0;");
        }
        __syncthreads();
        const uint32_t base = sb + st * 49152;
#pragma unroll
        for (int ks = 0; ks < 4; ks++) {
            uint32_t ah[2][4], al[2][4];
#pragma unroll
            for (int mt = 0; mt < 2; mt++) {
                int row = warp_m * 32 + mt * 16 + (lane & 15);
                int seg = ks * 2 + (lane >> 4);
                uint32_t off = SW128(row * 128 + seg * 16);
                ldm_x4(ah[mt], base + off);
                ldm_x4(al[mt], base + 16384 + off);
            }
            uint32_t bh_[2][4], bl_[2][4];
#pragma unroll
            for (int h = 0; h < 2; h++) {
                int row = warp_n * 32 + h * 16 + ((lane >> 4) & 1) * 8 + (lane & 7);
                int seg = ks * 2 + ((lane >> 3) & 1);
                uint32_t off = SW128(row * 128 + seg * 16);
                ldm_x4(bh_[h], base + 32768 + off);
                ldm_x4(bl_[h], base + 40960 + off);
            }
#pragma unroll
            for (int mt = 0; mt < 2; mt++)
#pragma unroll
                for (int nt = 0; nt < 4; nt++) {
                    uint32_t vh0 = bh_[nt >> 1][(nt & 1) * 2];
                    uint32_t vh1 = bh_[nt >> 1][(nt & 1) * 2 + 1];
                    uint32_t vl0 = bl_[nt >> 1][(nt & 1) * 2];
                    uint32_t vl1 = bl_[nt >> 1][(nt & 1) * 2 + 1];
                    mma_bf16(acc[mt][nt], ah[mt], vh0, vh1);
                    mma_bf16(acc[mt][nt], al[mt], vh0, vh1);
                    mma_bf16(acc[mt][nt], ah[mt], vl0, vl1);
                }
        }
        __syncthreads();
    }
#undef AV_LOAD

    const int bb = bh / NH, h = bh % NH;
    const int mrow = lane >> 2;
    const int ncol = 2 * (lane & 3);
#pragma unroll
    for (int mt = 0; mt < 2; mt++)
#pragma unroll
        for (int nt = 0; nt < 4; nt++) {
            int hd = warp_n * 32 + nt * 8 + ncol;
            int cc = h * HD + hd;
            int ch = cc >> 5, p = cc & 31;
#pragma unroll
            for (int half = 0; half < 2; half++) {
                int s = q0 + warp_m * 32 + mt * 16 + mrow + half * 8;
                float v0 = acc[mt][nt][half * 2];
                float v1 = acc[mt][nt][half * 2 + 1];
                __nv_bfloat16 h0 = __float2bfloat16(v0);
                __nv_bfloat16 h1 = __float2bfloat16(v1);
                __nv_bfloat16 l0 = __float2bfloat16(v0 - __bfloat162float(h0));
                __nv_bfloat16 l1 = __float2bfloat16(v1 - __bfloat162float(h1));
                size_t base = ((size_t)(bb * S_LEN + s)) * KC2 + ch * 64 + p;
                *(__nv_bfloat162*)&Acat[base]      = __halves2bfloat162(h0, h1);
                *(__nv_bfloat162*)&Acat[base + 32] = __halves2bfloat162(l0, l1);
            }
        }
}

// ---------------------------------------------------------------------------
extern "C" void kernel_launch(void* const* d_in, const int* in_sizes, int n_in,
                              void* d_out, int out_size)
{
    const float* X  = (const float*)d_in[0];
    const float* Wq = (const float*)d_in[1];
    const float* bq = (const float*)d_in[2];
    const float* Wk = (const float*)d_in[3];
    const float* bk = (const float*)d_in[4];
    const float* Wv = (const float*)d_in[5];
    const float* bv = (const float*)d_in[6];
    const float* Wo = (const float*)d_in[7];
    const float* bo = (const float*)d_in[8];

    float* out  = (float*)d_out;
    float* attn = out + (size_t)MROWS * DM;

    __nv_bfloat16 *gXc, *gAc, *gWq, *gWk, *gWv, *gWo;
    __nv_bfloat16 *gQc, *gKc, *gVh, *gVl, *gPh, *gPl;
    cudaGetSymbolAddress((void**)&gXc, g_Xcat);
    cudaGetSymbolAddress((void**)&gAc, g_Acat);
    cudaGetSymbolAddress((void**)&gWq, g_Wqc);
    cudaGetSymbolAddress((void**)&gWk, g_Wkc);
    cudaGetSymbolAddress((void**)&gWv, g_Wvc);
    cudaGetSymbolAddress((void**)&gWo, g_Woc);
    cudaGetSymbolAddress((void**)&gQc, g_Qc);
    cudaGetSymbolAddress((void**)&gKc, g_Kc);
    cudaGetSymbolAddress((void**)&gVh, g_Vth);
    cudaGetSymbolAddress((void**)&gVl, g_Vtl);
    cudaGetSymbolAddress((void**)&gPh, g_Ph);
    cudaGetSymbolAddress((void**)&gPl, g_Pl);

    static int init_done = 0;
    if (!init_done) {
        cudaFuncSetAttribute(gemm_qkv, cudaFuncAttributeMaxDynamicSharedMemorySize, GEMM_SMEM);
        cudaFuncSetAttribute(gemm_mma, cudaFuncAttributeMaxDynamicSharedMemorySize, GEMM_SMEM);
        cudaFuncSetAttribute(scores_mma, cudaFuncAttributeMaxDynamicSharedMemorySize, SC_SMEM);
        cudaFuncSetAttribute(av_mma, cudaFuncAttributeMaxDynamicSharedMemorySize, AV_SMEM);
        init_done = 1;
    }

    dim3 blk(256);

    // converts (X + all four weights)
    convert_cat<<<1024, blk>>>(X, gXc, MROWS);
    dim3 gw(256, 4);
    convert_w4<<<gw, blk>>>(Wq, Wk, Wv, Wo, gWq, gWk, gWv, gWo);

    // QKV projections in ONE launch (z selects operand)
    dim3 gqkv(DM / 128, MROWS / 128, 3);
    gemm_qkv<<<gqkv, blk, GEMM_SMEM>>>(gXc, gWq, gWk, gWv, bq, bk, bv,
                                       gQc, gKc, gVh, gVl);

    dim3 gsc(S_LEN / 128, S_LEN / 128, BHN);
    scores_mma<<<gsc, blk, SC_SMEM>>>(gQc, gKc, attn);

    dim3 gsm(S_LEN, BHN);
    softmax_kernel<<<gsm, blk>>>(attn, gPh, gPl);

    dim3 gav(S_LEN / 128, BHN);
    av_mma<<<gav, blk, AV_SMEM>>>(gPh, gPl, gVh, gVl, gAc);

    dim3 ggemm(DM / 128, MROWS / 128);
    gemm_mma<<<ggemm, blk, GEMM_SMEM>>>(gAc, gWo, bo, out);
}

// round 14
// speedup vs baseline: 1.1581x; 1.0522x over previous
#include <cuda_runtime.h>
#include <cuda_bf16.h>
#include <math.h>
#include <stdint.h>

#define S_LEN 2048
#define DM    1024
#define NH    16
#define HD    64
#define BATCH 2
#define BHN   (BATCH * NH)        // 32
#define MROWS (BATCH * S_LEN)     // 4096
#define KC2   2048                // [hi|lo] interleaved per 32-k chunk
#define NCH2  32                  // 32 chunks of 32 k-elems
#define QK2   128                 // Q/K row: [hi 64 | lo 64]

// ---------------- scratch (__device__ globals) ------------------------------
__device__ __nv_bfloat16 g_Xcat[(size_t)MROWS * KC2];
__device__ __nv_bfloat16 g_Acat[(size_t)MROWS * KC2];
__device__ __nv_bfloat16 g_Wqc[(size_t)DM * KC2];
__device__ __nv_bfloat16 g_Wkc[(size_t)DM * KC2];
__device__ __nv_bfloat16 g_Wvc[(size_t)DM * KC2];
__device__ __nv_bfloat16 g_Woc[(size_t)DM * KC2];
__device__ __nv_bfloat16 g_Qc[(size_t)BHN * S_LEN * QK2];   // [hi|lo]
__device__ __nv_bfloat16 g_Kc[(size_t)BHN * S_LEN * QK2];   // [hi|lo]
__device__ __nv_bfloat16 g_Vth[(size_t)BHN * HD * S_LEN];   // V^T hi
__device__ __nv_bfloat16 g_Vtl[(size_t)BHN * HD * S_LEN];   // V^T lo
__device__ __nv_bfloat16 g_Ph[(size_t)BHN * S_LEN * S_LEN]; // P hi
__device__ __nv_bfloat16 g_Pl[(size_t)BHN * S_LEN * S_LEN]; // P lo

// ---------------- helpers ---------------------------------------------------
__device__ __forceinline__ uint32_t smem_u32(const void* p) {
    uint32_t a;
    asm("{ .reg .u64 t; cvta.to.shared.u64 t, %1; cvt.u32.u64 %0, t; }"
        : "=r"(a) : "l"(p));
    return a;
}
#define SW128(o) ((o) ^ (((o) >> 3) & 0x70))

__device__ __forceinline__ void ldm_x4(uint32_t* r, uint32_t addr) {
    asm volatile("ldmatrix.sync.aligned.m8n8.x4.shared.b16 {%0,%1,%2,%3}, [%4];"
                 : "=r"(r[0]), "=r"(r[1]), "=r"(r[2]), "=r"(r[3]) : "r"(addr));
}
__device__ __forceinline__ void mma_bf16(float* c, const uint32_t* a,
                                         uint32_t b0, uint32_t b1) {
    asm volatile(
        "mma.sync.aligned.m16n8k16.row.col.f32.bf16.bf16.f32 "
        "{%0,%1,%2,%3}, {%4,%5,%6,%7}, {%8,%9}, {%0,%1,%2,%3};"
        : "+f"(c[0]), "+f"(c[1]), "+f"(c[2]), "+f"(c[3])
        : "r"(a[0]), "r"(a[1]), "r"(a[2]), "r"(a[3]), "r"(b0), "r"(b1));
}
#define CP16(dst, src) \
    asm volatile("cp.async.cg.shared.global [%0], [%1], 16;" :: "r"(dst), "l"(src))
#define CP_COMMIT() asm volatile("cp.async.commit_group;")

// ---------------------------------------------------------------------------
// fp32 [rows,1024] -> bf16 [rows,2048], per-32-chunk interleave [hi32|lo32].
// ---------------------------------------------------------------------------
__device__ __forceinline__ void conv_body(
    const float* __restrict__ src, __nv_bfloat16* __restrict__ dst,
    int rows, int gid, int gstride)
{
    int n = rows * (DM / 4);
    for (int i = gid; i < n; i += gstride) {
        int r = i / (DM / 4), cq = i - r * (DM / 4);
        float4 v = *(const float4*)&src[(size_t)r * DM + cq * 4];
        float f[4] = {v.x, v.y, v.z, v.w};
        __nv_bfloat16 hi[4], lo[4];
#pragma unroll
        for (int j = 0; j < 4; j++) {
            hi[j] = __float2bfloat16(f[j]);
            lo[j] = __float2bfloat16(f[j] - __bfloat162float(hi[j]));
        }
        int c = cq >> 3;
        int p = (cq & 7) * 4;
        size_t base = (size_t)r * KC2 + c * 64 + p;
        *(__nv_bfloat162*)&dst[base]      = __halves2bfloat162(hi[0], hi[1]);
        *(__nv_bfloat162*)&dst[base + 2]  = __halves2bfloat162(hi[2], hi[3]);
        *(__nv_bfloat162*)&dst[base + 32] = __halves2bfloat162(lo[0], lo[1]);
        *(__nv_bfloat162*)&dst[base + 34] = __halves2bfloat162(lo[2], lo[3]);
    }
}

__global__ __launch_bounds__(256) void convert_cat(
    const float* __restrict__ src, __nv_bfloat16* __restrict__ dst, int rows)
{
    conv_body(src, dst, rows, blockIdx.x * blockDim.x + threadIdx.x,
              gridDim.x * blockDim.x);
}

__global__ __launch_bounds__(256) void convert_w4(
    const float* __restrict__ w0, const float* __restrict__ w1,
    const float* __restrict__ w2, const float* __restrict__ w3,
    __nv_bfloat16* __restrict__ d0, __nv_bfloat16* __restrict__ d1,
    __nv_bfloat16* __restrict__ d2, __nv_bfloat16* __restrict__ d3)
{
    const float* src = (blockIdx.y == 0) ? w0 : (blockIdx.y == 1) ? w1
                     : (blockIdx.y == 2) ? w2 : w3;
    __nv_bfloat16* dst = (blockIdx.y == 0) ? d0 : (blockIdx.y == 1) ? d1
                       : (blockIdx.y == 2) ? d2 : d3;
    conv_body(src, dst, DM, blockIdx.x * blockDim.x + threadIdx.x,
              gridDim.x * blockDim.x);
}

// ---------------------------------------------------------------------------
// GEMM mainloop: 3-stage cp.async, single barrier per chunk.
// ---------------------------------------------------------------------------
#define GEMM_SMEM 98304   // A: 3x16K at 0, B: 3x16K at 49152

#define GEMM_MAIN(Aptr, Bptr)                                                  \
    float acc[4][4][4] = {};                                                   \
    {                                                                          \
        _Pragma("unroll")                                                      \
        for (int pc = 0; pc < 2; pc++) {                                       \
            uint32_t ab = sb + pc * 16384;                                     \
            uint32_t bb = sb + 49152 + pc * 16384;                             \
            size_t kb = (size_t)pc * 64 + ls * 8;                              \
            _Pragma("unroll")                                                  \
            for (int i_ = 0; i_ < 4; i_++) {                                   \
                int r_ = lr + 32 * i_;                                         \
                uint32_t off = SW128(r_ * 128 + ls * 16);                      \
                CP16(ab + off, &Aptr[(size_t)(r0 + r_) * KC2 + kb]);           \
                CP16(bb + off, &Bptr[(size_t)(c0 + r_) * KC2 + kb]);           \
            }                                                                  \
            CP_COMMIT();                                                       \
        }                                                                      \
    }                                                                          \
    int st = 0, st2 = 2;                                                       \
    for (int c = 0; c < NCH2; c++) {                                           \
        if (c + 2 < NCH2) asm volatile("cp.async.wait_group 1;");              \
        else              asm volatile("cp.async.wait_group 0;");              \
        __syncthreads();                                                       \
        if (c + 2 < NCH2) {                                                    \
            uint32_t ab = sb + st2 * 16384;                                    \
            uint32_t bb = sb + 49152 + st2 * 16384;                            \
            size_t kb = (size_t)(c + 2) * 64 + ls * 8;                         \
            _Pragma("unroll")                                                  \
            for (int i_ = 0; i_ < 4; i_++) {                                   \
                int r_ = lr + 32 * i_;                                         \
                uint32_t off = SW128(r_ * 128 + ls * 16);                      \
                CP16(ab + off, &Aptr[(size_t)(r0 + r_) * KC2 + kb]);           \
                CP16(bb + off, &Bptr[(size_t)(c0 + r_) * KC2 + kb]);           \
            }                                                                  \
            CP_COMMIT();                                                       \
        }                                                                      \
        const uint32_t abase = sb + st * 16384;                                \
        const uint32_t bbase = sb + 49152 + st * 16384;                        \
        _Pragma("unroll")                                                      \
        for (int ks = 0; ks < 2; ks++) {                                       \
            uint32_t af[4][4];                                                 \
            uint32_t bhf[2][4], blf[2][4];                                     \
            _Pragma("unroll")                                                  \
            for (int mt = 0; mt < 4; mt++) {                                   \
                int row = warp_m * 64 + mt * 16 + (lane & 15);                 \
                int seg = ks * 2 + (lane >> 4);                                \
                ldm_x4(af[mt], abase + SW128(row * 128 + seg * 16));           \
            }                                                                  \
            _Pragma("unroll")                                                  \
            for (int h = 0; h < 2; h++) {                                      \
                int row = warp_n * 32 + h * 16 + ((lane >> 4) & 1) * 8 + (lane & 7); \
                int seg = ks * 2 + ((lane >> 3) & 1);                          \
                uint32_t off = row * 128 + seg * 16;                           \
                ldm_x4(bhf[h], bbase + SW128(off));                            \
                ldm_x4(blf[h], bbase + SW128(off + 64));                       \
            }                                                                  \
            _Pragma("unroll")                                                  \
            for (int mt = 0; mt < 4; mt++)                                     \
                _Pragma("unroll")                                              \
                for (int nt = 0; nt < 4; nt++)                                 \
                    mma_bf16(acc[mt][nt], af[mt],                              \
                             bhf[nt >> 1][(nt & 1) * 2], bhf[nt >> 1][(nt & 1) * 2 + 1]); \
            _Pragma("unroll")                                                  \
            for (int mt = 0; mt < 4; mt++)                                     \
                _Pragma("unroll")                                              \
                for (int nt = 0; nt < 4; nt++)                                 \
                    mma_bf16(acc[mt][nt], af[mt],                              \
                             blf[nt >> 1][(nt & 1) * 2], blf[nt >> 1][(nt & 1) * 2 + 1]); \
            _Pragma("unroll")                                                  \
            for (int mt = 0; mt < 4; mt++) {                                   \
                int row = warp_m * 64 + mt * 16 + (lane & 15);                 \
                int seg = 4 + ks * 2 + (lane >> 4);                            \
                ldm_x4(af[mt], abase + SW128(row * 128 + seg * 16));           \
            }                                                                  \
            _Pragma("unroll")                                                  \
            for (int mt = 0; mt < 4; mt++)                                     \
                _Pragma("unroll")                                              \
                for (int nt = 0; nt < 4; nt++)                                 \
                    mma_bf16(acc[mt][nt], af[mt],                              \
                             bhf[nt >> 1][(nt & 1) * 2], bhf[nt >> 1][(nt & 1) * 2 + 1]); \
        }                                                                      \
        st  = (st  == 2) ? 0 : st + 1;                                         \
        st2 = (st2 == 2) ? 0 : st2 + 1;                                        \
    }

// ---------------------------------------------------------------------------
// gemm_qkv: z = blockIdx.z + zoff selects operand.
// z=0 -> Q [hi|lo]; z=1 -> K [hi|lo]; z=2 -> V^T hi/lo planes.
// ---------------------------------------------------------------------------
__global__ void __launch_bounds__(256, 2) gemm_qkv(
    const __nv_bfloat16* __restrict__ A,
    const __nv_bfloat16* __restrict__ Bq, const __nv_bfloat16* __restrict__ Bk,
    const __nv_bfloat16* __restrict__ Bv,
    const float* __restrict__ bq, const float* __restrict__ bk,
    const float* __restrict__ bv,
    __nv_bfloat16* __restrict__ oQ, __nv_bfloat16* __restrict__ oK,
    __nv_bfloat16* __restrict__ oVh, __nv_bfloat16* __restrict__ oVl, int zoff)
{
    extern __shared__ __align__(1024) char smem[];
    const int z = blockIdx.z + zoff;
    const __nv_bfloat16* B = (z == 0) ? Bq : (z == 1) ? Bk : Bv;
    const float* bias = (z == 0) ? bq : (z == 1) ? bk : bv;

    const int tid = threadIdx.x;
    const int wid = tid >> 5, lane = tid & 31;
    const int warp_m = wid >> 2;
    const int warp_n = wid & 3;
    const uint32_t sb = smem_u32(smem);
    const int r0 = blockIdx.y * 128, c0 = blockIdx.x * 128;
    const int ls = tid & 7;
    const int lr = tid >> 3;

    GEMM_MAIN(A, B)

    const int mrow = lane >> 2;
    const int ncol = 2 * (lane & 3);
#pragma unroll
    for (int mt = 0; mt < 4; mt++) {
#pragma unroll
        for (int nt = 0; nt < 4; nt++) {
            int cg = c0 + warp_n * 32 + nt * 8 + ncol;
            float b0 = __ldg(&bias[cg]), b1 = __ldg(&bias[cg + 1]);
#pragma unroll
            for (int half = 0; half < 2; half++) {
                int r = r0 + warp_m * 64 + mt * 16 + mrow + half * 8;
                float v0 = acc[mt][nt][half * 2] + b0;
                float v1 = acc[mt][nt][half * 2 + 1] + b1;
                int bb = r >> 11, s = r & (S_LEN - 1);
                int h = cg >> 6, hd = cg & 63;
                __nv_bfloat16 h0 = __float2bfloat16(v0);
                __nv_bfloat16 h1 = __float2bfloat16(v1);
                __nv_bfloat16 l0 = __float2bfloat16(v0 - __bfloat162float(h0));
                __nv_bfloat16 l1 = __float2bfloat16(v1 - __bfloat162float(h1));
                if (z == 2) {
                    size_t pb = ((size_t)(bb * NH + h) * HD + hd) * S_LEN + s;
                    oVh[pb] = h0; oVh[pb + S_LEN] = h1;
                    oVl[pb] = l0; oVl[pb + S_LEN] = l1;
                } else {
                    __nv_bfloat16* ob = (z == 0) ? oQ : oK;
                    size_t base = ((size_t)(bb * NH + h) * S_LEN + s) * QK2 + hd;
                    *(__nv_bfloat162*)&ob[base]      = __halves2bfloat162(h0, h1);
                    *(__nv_bfloat162*)&ob[base + 64] = __halves2bfloat162(l0, l1);
                }
            }
        }
    }
}

// ---------------------------------------------------------------------------
// gemm_mma: Wo projection, fp32 row-major output.
// ---------------------------------------------------------------------------
__global__ void __launch_bounds__(256, 2) gemm_mma(
    const __nv_bfloat16* __restrict__ A, const __nv_bfloat16* __restrict__ B,
    const float* __restrict__ bias, float* __restrict__ outf)
{
    extern __shared__ __align__(1024) char smem[];
    const int tid = threadIdx.x;
    const int wid = tid >> 5, lane = tid & 31;
    const int warp_m = wid >> 2;
    const int warp_n = wid & 3;
    const uint32_t sb = smem_u32(smem);
    const int r0 = blockIdx.y * 128, c0 = blockIdx.x * 128;
    const int ls = tid & 7;
    const int lr = tid >> 3;

    GEMM_MAIN(A, B)

    const int mrow = lane >> 2;
    const int ncol = 2 * (lane & 3);
#pragma unroll
    for (int mt = 0; mt < 4; mt++) {
#pragma unroll
        for (int nt = 0; nt < 4; nt++) {
            int cg = c0 + warp_n * 32 + nt * 8 + ncol;
            float b0 = __ldg(&bias[cg]), b1 = __ldg(&bias[cg + 1]);
#pragma unroll
            for (int half = 0; half < 2; half++) {
                int r = r0 + warp_m * 64 + mt * 16 + mrow + half * 8;
                float2 v = {acc[mt][nt][half * 2] + b0,
                            acc[mt][nt][half * 2 + 1] + b1};
                *(float2*)&outf[(size_t)r * DM + cg] = v;
            }
        }
    }
}

// ---------------------------------------------------------------------------
// scores_mma: attn = 0.125 * (Qh*Kh + Qh*Kl + Ql*Kh).  Q/K rows [hi|lo] (128).
// Upper-triangle CTAs (kt > qt) zero-fill their attn tile instead of exiting.
// ---------------------------------------------------------------------------
#define SC_SMEM 65536

__global__ __launch_bounds__(256) void scores_mma(
    const __nv_bfloat16* __restrict__ Qc, const __nv_bfloat16* __restrict__ Kc,
    float* __restrict__ attn)
{
    const int kt = blockIdx.x, qt = blockIdx.y, bh = blockIdx.z;
    const int q0 = qt * 128, c0 = kt * 128;
    float* Arow = attn + (size_t)bh * S_LEN * S_LEN;

    if (kt > qt) {
        const float4 z = {0.f, 0.f, 0.f, 0.f};
        const int tid = threadIdx.x;
        for (int idx = tid; idx < 128 * 32; idx += 256) {
            int r = idx >> 5, c = (idx & 31) * 4;
            *(float4*)&Arow[(size_t)(q0 + r) * S_LEN + c0 + c] = z;
        }
        return;
    }

    extern __shared__ __align__(1024) char smem[];
    const int tid = threadIdx.x;
    const int wid = tid >> 5, lane = tid & 31;
    const int warp_m = wid >> 2;
    const int warp_n = wid & 3;
    const uint32_t sb = smem_u32(smem);

    const __nv_bfloat16* Qb = Qc + (size_t)bh * S_LEN * QK2;
    const __nv_bfloat16* Kb = Kc + (size_t)bh * S_LEN * QK2;
    const int ls = tid & 7;
    const int lr = tid >> 3;

#pragma unroll
    for (int i_ = 0; i_ < 4; i_++) {
        int r_ = lr + 32 * i_;
        uint32_t off = SW128(r_ * 128 + ls * 16);
        CP16(sb + off,         &Qb[(size_t)(q0 + r_) * QK2 + ls * 8]);
        CP16(sb + 16384 + off, &Qb[(size_t)(q0 + r_) * QK2 + 64 + ls * 8]);
        CP16(sb + 32768 + off, &Kb[(size_t)(c0 + r_) * QK2 + ls * 8]);
        CP16(sb + 49152 + off, &Kb[(size_t)(c0 + r_) * QK2 + 64 + ls * 8]);
    }
    CP_COMMIT();
    asm volatile("cp.async.wait_group 0;");
    __syncthreads();

    float acc[4][4][4] = {};
#pragma unroll
    for (int ks = 0; ks < 4; ks++) {
        uint32_t af[4][4], bh[2][4], bl[2][4];
#pragma unroll
        for (int mt = 0; mt < 4; mt++) {
            int row = warp_m * 64 + mt * 16 + (lane & 15);
            int seg = ks * 2 + (lane >> 4);
            ldm_x4(af[mt], sb + SW128(row * 128 + seg * 16));
        }
#pragma unroll
        for (int h = 0; h < 2; h++) {
            int row = warp_n * 32 + h * 16 + ((lane >> 4) & 1) * 8 + (lane & 7);
            int seg = ks * 2 + ((lane >> 3) & 1);
            uint32_t off = SW128(row * 128 + seg * 16);
            ldm_x4(bh[h], sb + 32768 + off);
            ldm_x4(bl[h], sb + 49152 + off);
        }
#pragma unroll
        for (int mt = 0; mt < 4; mt++)
#pragma unroll
            for (int nt = 0; nt < 4; nt++)
                mma_bf16(acc[mt][nt], af[mt],
                         bh[nt >> 1][(nt & 1) * 2], bh[nt >> 1][(nt & 1) * 2 + 1]);
#pragma unroll
        for (int mt = 0; mt < 4; mt++)
#pragma unroll
            for (int nt = 0; nt < 4; nt++)
                mma_bf16(acc[mt][nt], af[mt],
                         bl[nt >> 1][(nt & 1) * 2], bl[nt >> 1][(nt & 1) * 2 + 1]);
#pragma unroll
        for (int mt = 0; mt < 4; mt++) {
            int row = warp_m * 64 + mt * 16 + (lane & 15);
            int seg = ks * 2 + (lane >> 4);
            ldm_x4(af[mt], sb + 16384 + SW128(row * 128 + seg * 16));
        }
#pragma unroll
        for (int mt = 0; mt < 4; mt++)
#pragma unroll
            for (int nt = 0; nt < 4; nt++)
                mma_bf16(acc[mt][nt], af[mt],
                         bh[nt >> 1][(nt & 1) * 2], bh[nt >> 1][(nt & 1) * 2 + 1]);
    }

    const int mrow = lane >> 2;
    const int ncol = 2 * (lane & 3);
#pragma unroll
    for (int mt = 0; mt < 4; mt++)
#pragma unroll
        for (int nt = 0; nt < 4; nt++) {
            int cg = c0 + warp_n * 32 + nt * 8 + ncol;
#pragma unroll
            for (int half = 0; half < 2; half++) {
                int q = q0 + warp_m * 64 + mt * 16 + mrow + half * 8;
                float2 v = {acc[mt][nt][half * 2] * 0.125f,
                            acc[mt][nt][half * 2 + 1] * 0.125f};
                *(float2*)&Arow[(size_t)q * S_LEN + cg] = v;
            }
        }
}

// ---------------------------------------------------------------------------
// Row-wise causal softmax. fp32 probs + bf16 hi/lo planes, clipped to the
// 128-row tile's k boundary (scores' idle CTAs own k >= tile_kend).
// ---------------------------------------------------------------------------
__global__ __launch_bounds__(256) void softmax_kernel(
    float* __restrict__ attn, __nv_bfloat16* __restrict__ Ph,
    __nv_bfloat16* __restrict__ Pl)
{
    const int q = blockIdx.x, bh = blockIdx.y;
    const size_t rbase = ((size_t)bh * S_LEN + q) * S_LEN;
    float* row = attn + rbase;
    const int tid = threadIdx.x;
    const int valid = q + 1;
    const int tile_kend = (q & ~127) + 128;
    const int b0 = 4 * tid, b1 = 4 * (tid + 256);

    float4 v0 = {-INFINITY, -INFINITY, -INFINITY, -INFINITY}, v1 = v0;
    if (b0 < valid) v0 = *(const float4*)&row[b0];
    if (b1 < valid) v1 = *(const float4*)&row[b1];
    float vals[8] = {v0.x, v0.y, v0.z, v0.w, v1.x, v1.y, v1.z, v1.w};

    float mx = -INFINITY;
#pragma unroll
    for (int i = 0; i < 8; i++) {
        int k = (i < 4) ? (b0 + i) : (b1 + i - 4);
        if (k >= valid) vals[i] = -INFINITY;
        mx = fmaxf(mx, vals[i]);
    }
#pragma unroll
    for (int o = 16; o; o >>= 1) mx = fmaxf(mx, __shfl_xor_sync(~0u, mx, o));
    __shared__ float sred[8];
    if ((tid & 31) == 0) sred[tid >> 5] = mx;
    __syncthreads();
    mx = sred[0];
#pragma unroll
    for (int i = 1; i < 8; i++) mx = fmaxf(mx, sred[i]);
    __syncthreads();

    float sum = 0.f;
#pragma unroll
    for (int i = 0; i < 8; i++) {
        float e = __expf(vals[i] - mx);
        vals[i] = e;
        sum += e;
    }
#pragma unroll
    for (int o = 16; o; o >>= 1) sum += __shfl_xor_sync(~0u, sum, o);
    if ((tid & 31) == 0) sred[tid >> 5] = sum;
    __syncthreads();
    sum = 0.f;
#pragma unroll
    for (int i = 0; i < 8; i++) sum += sred[i];
    const float inv = 1.f / sum;

    float p[8];
    __nv_bfloat16 hh[8], ll[8];
#pragma unroll
    for (int i = 0; i < 8; i++) {
        p[i] = vals[i] * inv;
        hh[i] = __float2bfloat16(p[i]);
        ll[i] = __float2bfloat16(p[i] - __bfloat162float(hh[i]));
    }
    if (b0 < tile_kend) {
        float4 w0 = {p[0], p[1], p[2], p[3]};
        *(float4*)&row[b0] = w0;
#pragma unroll
        for (int j = 0; j < 2; j++) {
            *(__nv_bfloat162*)&Ph[rbase + b0 + 2*j] = __halves2bfloat162(hh[2*j], hh[2*j+1]);
            *(__nv_bfloat162*)&Pl[rbase + b0 + 2*j] = __halves2bfloat162(ll[2*j], ll[2*j+1]);
        }
    }
    if (b1 < tile_kend) {
        float4 w1 = {p[4], p[5], p[6], p[7]};
        *(float4*)&row[b1] = w1;
#pragma unroll
        for (int j = 0; j < 2; j++) {
            *(__nv_bfloat162*)&Ph[rbase + b1 + 2*j] = __halves2bfloat162(hh[4+2*j], hh[5+2*j]);
            *(__nv_bfloat162*)&Pl[rbase + b1 + 2*j] = __halves2bfloat162(ll[4+2*j], ll[5+2*j]);
        }
    }
}

// ---------------------------------------------------------------------------
// av_mma: A[q,hd] = Ph*Vh + Pl*Vh + Ph*Vl; causal chunk bound; 2 CTAs/SM.
// Writes A in [hi|lo]-interleaved layout for the Wo GEMM.
// ---------------------------------------------------------------------------
#define AV_SMEM 98304

__global__ void __launch_bounds__(256, 2) av_mma(
    const __nv_bfloat16* __restrict__ Ph, const __nv_bfloat16* __restrict__ Pl,
    const __nv_bfloat16* __restrict__ Vth, const __nv_bfloat16* __restrict__ Vtl,
    __nv_bfloat16* __restrict__ Acat)
{
    const int qt = blockIdx.x, bh = blockIdx.y;
    extern __shared__ __align__(1024) char smem[];
    const int tid = threadIdx.x;
    const int wid = tid >> 5, lane = tid & 31;
    const int warp_m = wid & 3;
    const int warp_n = wid >> 2;
    const uint32_t sb = smem_u32(smem);
    const int q0 = qt * 128;

    const __nv_bfloat16* Phb = Ph + (size_t)bh * S_LEN * S_LEN;
    const __nv_bfloat16* Plb = Pl + (size_t)bh * S_LEN * S_LEN;
    const __nv_bfloat16* Vhb = Vth + (size_t)bh * HD * S_LEN;
    const __nv_bfloat16* Vlb = Vtl + (size_t)bh * HD * S_LEN;

    const int ls = tid & 7;
    const int lr = tid >> 3;
    const int nch = (q0 + 128) / 64;

#define AV_LOAD(chunk, stage) do {                                             \
        uint32_t base = sb + (stage) * 49152;                                  \
        size_t kb = (size_t)(chunk) * 64 + ls * 8;                             \
        _Pragma("unroll")                                                      \
        for (int i_ = 0; i_ < 4; i_++) {                                       \
            int r_ = lr + 32 * i_;                                             \
            uint32_t off = SW128(r_ * 128 + ls * 16);                          \
            CP16(base + off,         &Phb[(size_t)(q0 + r_) * S_LEN + kb]);    \
            CP16(base + 16384 + off, &Plb[(size_t)(q0 + r_) * S_LEN + kb]);    \
        }                                                                      \
        _Pragma("unroll")                                                      \
        for (int i_ = 0; i_ < 2; i_++) {                                       \
            int r_ = lr + 32 * i_;                                             \
            uint32_t off = SW128(r_ * 128 + ls * 16);                          \
            CP16(base + 32768 + off, &Vhb[(size_t)r_ * S_LEN + kb]);           \
            CP16(base + 40960 + off, &Vlb[(size_t)r_ * S_LEN + kb]);           \
        }                                                                      \
        CP_COMMIT();                                                           \
    } while (0)

    float acc[2][4][4] = {};
    AV_LOAD(0, 0);
    for (int c = 0; c < nch; c++) {
        const int st = c & 1;
        if (c + 1 < nch) {
            AV_LOAD(c + 1, st ^ 1);
            asm volatile("cp.async.wait_group 1;");
        } else {
            asm volatile("cp.async.wait_group 0;");
        }
        __syncthreads();
        const uint32_t base = sb + st * 49152;
#pragma unroll
        for (int ks = 0; ks < 4; ks++) {
            uint32_t ah[2][4], al[2][4];
#pragma unroll
            for (int mt = 0; mt < 2; mt++) {
                int row = warp_m * 32 + mt * 16 + (lane & 15);
                int seg = ks * 2 + (lane >> 4);
                uint32_t off = SW128(row * 128 + seg * 16);
                ldm_x4(ah[mt], base + off);
                ldm_x4(al[mt], base + 16384 + off);
            }
            uint32_t bh_[2][4], bl_[2][4];
#pragma unroll
            for (int h = 0; h < 2; h++) {
                int row = warp_n * 32 + h * 16 + ((lane >> 4) & 1) * 8 + (lane & 7);
                int seg = ks * 2 + ((lane >> 3) & 1);
                uint32_t off = SW128(row * 128 + seg * 16);
                ldm_x4(bh_[h], base + 32768 + off);
                ldm_x4(bl_[h], base + 40960 + off);
            }
#pragma unroll
            for (int mt = 0; mt < 2; mt++)
#pragma unroll
                for (int nt = 0; nt < 4; nt++) {
                    uint32_t vh0 = bh_[nt >> 1][(nt & 1) * 2];
                    uint32_t vh1 = bh_[nt >> 1][(nt & 1) * 2 + 1];
                    uint32_t vl0 = bl_[nt >> 1][(nt & 1) * 2];
                    uint32_t vl1 = bl_[nt >> 1][(nt & 1) * 2 + 1];
                    mma_bf16(acc[mt][nt], ah[mt], vh0, vh1);
                    mma_bf16(acc[mt][nt], al[mt], vh0, vh1);
                    mma_bf16(acc[mt][nt], ah[mt], vl0, vl1);
                }
        }
        __syncthreads();
    }
#undef AV_LOAD

    const int bb = bh / NH, h = bh % NH;
    const int mrow = lane >> 2;
    const int ncol = 2 * (lane & 3);
#pragma unroll
    for (int mt = 0; mt < 2; mt++)
#pragma unroll
        for (int nt = 0; nt < 4; nt++) {
            int hd = warp_n * 32 + nt * 8 + ncol;
            int cc = h * HD + hd;
            int ch = cc >> 5, p = cc & 31;
#pragma unroll
            for (int half = 0; half < 2; half++) {
                int s = q0 + warp_m * 32 + mt * 16 + mrow + half * 8;
                float v0 = acc[mt][nt][half * 2];
                float v1 = acc[mt][nt][half * 2 + 1];
                __nv_bfloat16 h0 = __float2bfloat16(v0);
                __nv_bfloat16 h1 = __float2bfloat16(v1);
                __nv_bfloat16 l0 = __float2bfloat16(v0 - __bfloat162float(h0));
                __nv_bfloat16 l1 = __float2bfloat16(v1 - __bfloat162float(h1));
                size_t base = ((size_t)(bb * S_LEN + s)) * KC2 + ch * 64 + p;
                *(__nv_bfloat162*)&Acat[base]      = __halves2bfloat162(h0, h1);
                *(__nv_bfloat162*)&Acat[base + 32] = __halves2bfloat162(l0, l1);
            }
        }
}

// ---------------------------------------------------------------------------
extern "C" void kernel_launch(void* const* d_in, const int* in_sizes, int n_in,
                              void* d_out, int out_size)
{
    const float* X  = (const float*)d_in[0];
    const float* Wq = (const float*)d_in[1];
    const float* bq = (const float*)d_in[2];
    const float* Wk = (const float*)d_in[3];
    const float* bk = (const float*)d_in[4];
    const float* Wv = (const float*)d_in[5];
    const float* bv = (const float*)d_in[6];
    const float* Wo = (const float*)d_in[7];
    const float* bo = (const float*)d_in[8];

    float* out  = (float*)d_out;
    float* attn = out + (size_t)MROWS * DM;

    __nv_bfloat16 *gXc, *gAc, *gWq, *gWk, *gWv, *gWo;
    __nv_bfloat16 *gQc, *gKc, *gVh, *gVl, *gPh, *gPl;
    cudaGetSymbolAddress((void**)&gXc, g_Xcat);
    cudaGetSymbolAddress((void**)&gAc, g_Acat);
    cudaGetSymbolAddress((void**)&gWq, g_Wqc);
    cudaGetSymbolAddress((void**)&gWk, g_Wkc);
    cudaGetSymbolAddress((void**)&gWv, g_Wvc);
    cudaGetSymbolAddress((void**)&gWo, g_Woc);
    cudaGetSymbolAddress((void**)&gQc, g_Qc);
    cudaGetSymbolAddress((void**)&gKc, g_Kc);
    cudaGetSymbolAddress((void**)&gVh, g_Vth);
    cudaGetSymbolAddress((void**)&gVl, g_Vtl);
    cudaGetSymbolAddress((void**)&gPh, g_Ph);
    cudaGetSymbolAddress((void**)&gPl, g_Pl);

    static cudaStream_t s1;
    static cudaEvent_t evC, evV;
    static int init_done = 0;
    if (!init_done) {
        cudaFuncSetAttribute(gemm_qkv, cudaFuncAttributeMaxDynamicSharedMemorySize, GEMM_SMEM);
        cudaFuncSetAttribute(gemm_mma, cudaFuncAttributeMaxDynamicSharedMemorySize, GEMM_SMEM);
        cudaFuncSetAttribute(scores_mma, cudaFuncAttributeMaxDynamicSharedMemorySize, SC_SMEM);
        cudaFuncSetAttribute(av_mma, cudaFuncAttributeMaxDynamicSharedMemorySize, AV_SMEM);
        cudaStreamCreateWithFlags(&s1, cudaStreamNonBlocking);
        cudaEventCreateWithFlags(&evC, cudaEventDisableTiming);
        cudaEventCreateWithFlags(&evV, cudaEventDisableTiming);
        init_done = 1;
    }

    dim3 blk(256);

    // converts (X + all four weights) on main
    convert_cat<<<1024, blk>>>(X, gXc, MROWS);
    dim3 gw(256, 4);
    convert_w4<<<gw, blk>>>(Wq, Wk, Wv, Wo, gWq, gWk, gWv, gWo);
    cudaEventRecord(evC, 0);

    // Q,K projections on main (512 CTAs)
    dim3 gqk(DM / 128, MROWS / 128, 2);
    gemm_qkv<<<gqk, blk, GEMM_SMEM>>>(gXc, gWq, gWk, gWv, bq, bk, bv,
                                      gQc, gKc, gVh, gVl, 0);

    // V projection on side stream (256 CTAs) — overlaps scores' DRAM phase
    cudaStreamWaitEvent(s1, evC, 0);
    dim3 gv(DM / 128, MROWS / 128, 1);
    gemm_qkv<<<gv, blk, GEMM_SMEM, s1>>>(gXc, gWq, gWk, gWv, bq, bk, bv,
                                         gQc, gKc, gVh, gVl, 2);
    cudaEventRecord(evV, s1);

    dim3 gsc(S_LEN / 128, S_LEN / 128, BHN);
    scores_mma<<<gsc, blk, SC_SMEM>>>(gQc, gKc, attn);

    dim3 gsm(S_LEN, BHN);
    softmax_kernel<<<gsm, blk>>>(attn, gPh, gPl);

    cudaStreamWaitEvent(0, evV, 0);
    dim3 gav(S_LEN / 128, BHN);
    av_mma<<<gav, blk, AV_SMEM>>>(gPh, gPl, gVh, gVl, gAc);

    dim3 ggemm(DM / 128, MROWS / 128);
    gemm_mma<<<ggemm, blk, GEMM_SMEM>>>(gAc, gWo, bo, out);
}